// round 1
// baseline (speedup 1.0000x reference)
#include <cuda_runtime.h>
#include <math.h>

#define MAXN 100000
#define MAXE 600000

// ---------------- scratch (no allocations allowed) ----------------
__device__ float  g_hcat[(size_t)MAXN * 512];   // h0|h1|h2|h3 concatenated per node
__device__ float  g_z   [(size_t)MAXN * 128];   // (1+eps)h + agg
__device__ float  g_t1  [(size_t)MAXN * 256];   // after mlp1
__device__ float  g_z2  [(size_t)MAXN * 128];   // after mlp2
__device__ float  g_o1  [(size_t)MAXN * 128];   // relu(cat@W1+b1)
__device__ int    g_deg   [MAXN];
__device__ int    g_rowptr[MAXN + 1];
__device__ int    g_cursor[MAXN];
__device__ int    g_srcs  [MAXE];
__device__ float4 g_eas   [MAXE];               // permuted edge_attr (padded)
__device__ float  g_gsum  [64 * 128];
__device__ float  g_cnt   [64];

// ---------------- input projection: h0 = x @ in_W + in_b ----------------
__global__ void k_in_proj(const float* __restrict__ x, const float* __restrict__ W,
                          const float* __restrict__ b) {
    int node = blockIdx.x;
    int c = threadIdx.x;
    __shared__ float xs[12];
    if (c < 12) xs[c] = x[node * 12 + c];
    __syncthreads();
    float a = b[c];
#pragma unroll
    for (int k = 0; k < 12; k++) a += xs[k] * W[k * 128 + c];
    g_hcat[(size_t)node * 512 + c] = a;
}

// ---------------- CSR build (by dst) ----------------
__global__ void k_zero_deg(int n) {
    int i = blockIdx.x * blockDim.x + threadIdx.x;
    if (i < n) g_deg[i] = 0;
}
__global__ void k_count(const int* __restrict__ dst, int e) {
    int i = blockIdx.x * blockDim.x + threadIdx.x;
    if (i < e) atomicAdd(&g_deg[dst[i]], 1);
}
__global__ void k_scan(int n) {     // single block, 1024 threads
    __shared__ int ss[1024];
    int t = threadIdx.x;
    int chunk = (n + 1023) / 1024;
    int s0 = t * chunk, s1 = min(s0 + chunk, n);
    int s = 0;
    for (int i = s0; i < s1; i++) s += g_deg[i];
    ss[t] = s;
    __syncthreads();
    for (int off = 1; off < 1024; off <<= 1) {
        int v = (t >= off) ? ss[t - off] : 0;
        __syncthreads();
        ss[t] += v;
        __syncthreads();
    }
    int run = (t == 0) ? 0 : ss[t - 1];
    for (int i = s0; i < s1; i++) {
        g_rowptr[i] = run; g_cursor[i] = run; run += g_deg[i];
    }
    if (t == 0) g_rowptr[n] = ss[1023];
}
__global__ void k_scatter(const int* __restrict__ src, const int* __restrict__ dst,
                          const float* __restrict__ ea, int e) {
    int i = blockIdx.x * blockDim.x + threadIdx.x;
    if (i >= e) return;
    int d = dst[i];
    int p = atomicAdd(&g_cursor[d], 1);
    g_srcs[p] = src[i];
    float4 v; v.x = ea[3 * i]; v.y = ea[3 * i + 1]; v.z = ea[3 * i + 2]; v.w = 0.f;
    g_eas[p] = v;
}

// ---------------- per-layer aggregation: z = (1+eps)h + sum_in(h[src]+e) ----------------
// one warp per dst node, lane handles 4 columns (float4), edge-MLP in registers
__global__ void k_aggregate(const float* __restrict__ edgeW, const float* __restrict__ edgeb,
                            const float* __restrict__ eps, int l, int n) {
    int gid = blockIdx.x * blockDim.x + threadIdx.x;
    int node = gid >> 5, lane = gid & 31;
    if (node >= n) return;
    int c = lane * 4;
    float4 w0 = *(const float4*)(edgeW + c);
    float4 w1 = *(const float4*)(edgeW + 128 + c);
    float4 w2 = *(const float4*)(edgeW + 256 + c);
    float4 eb = *(const float4*)(edgeb + c);
    float ep = 1.f + eps[l];
    const float* hb = g_hcat + (size_t)l * 128;
    float4 hh = *(const float4*)(hb + (size_t)node * 512 + c);
    float4 acc = make_float4(ep * hh.x, ep * hh.y, ep * hh.z, ep * hh.w);
    int j0 = g_rowptr[node], j1 = g_rowptr[node + 1];
    for (int j = j0; j < j1; j++) {
        int s = g_srcs[j];
        float4 hs = *(const float4*)(hb + (size_t)s * 512 + c);
        float4 a = g_eas[j];
        acc.x += hs.x + w0.x * a.x + w1.x * a.y + w2.x * a.z + eb.x;
        acc.y += hs.y + w0.y * a.x + w1.y * a.y + w2.y * a.z + eb.y;
        acc.z += hs.z + w0.z * a.x + w1.z * a.y + w2.z * a.z + eb.z;
        acc.w += hs.w + w0.w * a.x + w1.w * a.y + w2.w * a.z + eb.w;
    }
    *(float4*)(g_z + (size_t)node * 128 + c) = acc;
}

// ---------------- SGEMM 128x128x16 tile, 8x8/thread, fused epilogue ----------------
// EPI: 0 = +bias, 1 = relu(+bias), 2 = relu(BN(+bias))
template<int EPI>
__global__ __launch_bounds__(256) void k_sgemm(
    const float* __restrict__ A, int lda,
    const float* __restrict__ Bm, int ldb,
    float* __restrict__ C, int ldc,
    int M, int K,
    const float* __restrict__ bias,
    const float* __restrict__ bng, const float* __restrict__ bnb,
    const float* __restrict__ bnrm, const float* __restrict__ bnrv) {
    __shared__ float As[16][128];
    __shared__ float Bs[16][128];
    int tid = threadIdx.x;
    int tx = tid & 15, ty = tid >> 4;
    int rowBase = blockIdx.y * 128;
    int colBase = blockIdx.x * 128;
    float acc[8][8];
#pragma unroll
    for (int i = 0; i < 8; i++)
#pragma unroll
        for (int j = 0; j < 8; j++) acc[i][j] = 0.f;

    for (int k0 = 0; k0 < K; k0 += 16) {
#pragma unroll
        for (int i = 0; i < 2; i++) {                 // A: 128x16 = 512 float4
            int v = tid + i * 256;
            int r = v >> 2, kk = (v & 3) << 2;
            int gr = rowBase + r;
            float4 f = make_float4(0.f, 0.f, 0.f, 0.f);
            if (gr < M) f = *(const float4*)(A + (size_t)gr * lda + k0 + kk);
            As[kk][r] = f.x; As[kk + 1][r] = f.y; As[kk + 2][r] = f.z; As[kk + 3][r] = f.w;
        }
#pragma unroll
        for (int i = 0; i < 2; i++) {                 // B: 16x128 = 512 float4
            int v = tid + i * 256;
            int kr = v >> 5, c4 = (v & 31) << 2;
            *(float4*)&Bs[kr][c4] = *(const float4*)(Bm + (size_t)(k0 + kr) * ldb + colBase + c4);
        }
        __syncthreads();
#pragma unroll
        for (int kk = 0; kk < 16; kk++) {
            float a[8], b[8];
            *(float4*)(a)     = *(const float4*)&As[kk][ty * 8];
            *(float4*)(a + 4) = *(const float4*)&As[kk][ty * 8 + 4];
            *(float4*)(b)     = *(const float4*)&Bs[kk][tx * 8];
            *(float4*)(b + 4) = *(const float4*)&Bs[kk][tx * 8 + 4];
#pragma unroll
            for (int i = 0; i < 8; i++)
#pragma unroll
                for (int j = 0; j < 8; j++)
                    acc[i][j] += a[i] * b[j];
        }
        __syncthreads();
    }

    float cs[8], ct[8];
#pragma unroll
    for (int j = 0; j < 8; j++) {
        int col = colBase + tx * 8 + j;
        if (EPI == 2) {
            float s = bng[col] * rsqrtf(bnrv[col] + 1e-5f);
            cs[j] = s; ct[j] = bnb[col] + (bias[col] - bnrm[col]) * s;
        } else { cs[j] = 1.f; ct[j] = bias[col]; }
    }
#pragma unroll
    for (int i = 0; i < 8; i++) {
        int gr = rowBase + ty * 8 + i;
        if (gr >= M) continue;
        float o[8];
#pragma unroll
        for (int j = 0; j < 8; j++) {
            float v = acc[i][j] * cs[j] + ct[j];
            if (EPI >= 1) v = fmaxf(v, 0.f);
            o[j] = v;
        }
        *(float4*)(C + (size_t)gr * ldc + colBase + tx * 8)     = *(float4*)o;
        *(float4*)(C + (size_t)gr * ldc + colBase + tx * 8 + 4) = *(float4*)(o + 4);
    }
}

// ---------------- residual + LayerNorm: h_{l+1} = LN(z2 + h_l) ----------------
__global__ void k_ln(const float* __restrict__ lng, const float* __restrict__ lnb, int l) {
    int node = blockIdx.x;
    int c = threadIdx.x;
    float v = g_z2[(size_t)node * 128 + c] + g_hcat[(size_t)node * 512 + l * 128 + c];
    float s = v, q = v * v;
#pragma unroll
    for (int o = 16; o > 0; o >>= 1) {
        s += __shfl_xor_sync(0xFFFFFFFFu, s, o);
        q += __shfl_xor_sync(0xFFFFFFFFu, q, o);
    }
    __shared__ float ss[4], sq[4];
    int w = c >> 5;
    if ((c & 31) == 0) { ss[w] = s; sq[w] = q; }
    __syncthreads();
    float ts = ss[0] + ss[1] + ss[2] + ss[3];
    float tq = sq[0] + sq[1] + sq[2] + sq[3];
    float mu = ts * (1.f / 128.f);
    float var = tq * (1.f / 128.f) - mu * mu;
    float r = rsqrtf(var + 1e-5f);
    g_hcat[(size_t)node * 512 + (l + 1) * 128 + c] = (v - mu) * r * lng[c] + lnb[c];
}

// ---------------- global mean pool ----------------
__global__ void k_zero_pool(int b) {
    int i = blockIdx.x * blockDim.x + threadIdx.x;
    if (i < b * 128) g_gsum[i] = 0.f;
    if (i < b) g_cnt[i] = 0.f;
}
__global__ void k_pool_acc(const float* __restrict__ emb, const int* __restrict__ batch, int n) {
    int c = threadIdx.x;                // 128 threads = columns
    int base = blockIdx.x * 64;         // 64 nodes per block, batch sorted -> run-length partials
    float acc = 0.f, cnt = 0.f;
    int cur = -1;
    for (int i = 0; i < 64; i++) {
        int nd = base + i;
        if (nd >= n) break;
        int g = batch[nd];
        if (g != cur) {
            if (cur >= 0) {
                atomicAdd(&g_gsum[cur * 128 + c], acc);
                if (c == 0) atomicAdd(&g_cnt[cur], cnt);
            }
            cur = g; acc = 0.f; cnt = 0.f;
        }
        acc += emb[(size_t)nd * 128 + c];
        cnt += 1.f;
    }
    if (cur >= 0) {
        atomicAdd(&g_gsum[cur * 128 + c], acc);
        if (c == 0) atomicAdd(&g_cnt[cur], cnt);
    }
}
__global__ void k_pool_fin(float* __restrict__ out, int b) {
    int i = blockIdx.x * blockDim.x + threadIdx.x;
    if (i >= b * 128) return;
    out[i] = g_gsum[i] / fmaxf(g_cnt[i >> 7], 1.f);
}

// ---------------- launch ----------------
extern "C" void kernel_launch(void* const* d_in, const int* in_sizes, int n_in,
                              void* d_out, int out_size) {
    const float* x      = (const float*)d_in[0];
    const int*   ei     = (const int*)d_in[1];
    const float* ea     = (const float*)d_in[2];
    const int*   batch  = (const int*)d_in[3];
    const float* in_W   = (const float*)d_in[4];
    const float* in_b   = (const float*)d_in[5];
    const float* edge_W = (const float*)d_in[6];
    const float* edge_b = (const float*)d_in[7];
    const float* mlp_W1 = (const float*)d_in[8];
    const float* mlp_b1 = (const float*)d_in[9];
    const float* bn1_g  = (const float*)d_in[10];
    const float* bn1_b  = (const float*)d_in[11];
    const float* bn1_rm = (const float*)d_in[12];
    const float* bn1_rv = (const float*)d_in[13];
    const float* mlp_W2 = (const float*)d_in[14];
    const float* mlp_b2 = (const float*)d_in[15];
    const float* bn2_g  = (const float*)d_in[16];
    const float* bn2_b  = (const float*)d_in[17];
    const float* bn2_rm = (const float*)d_in[18];
    const float* bn2_rv = (const float*)d_in[19];
    const float* eps    = (const float*)d_in[20];
    const float* ln_g   = (const float*)d_in[21];
    const float* ln_b   = (const float*)d_in[22];
    const float* out_W1 = (const float*)d_in[23];
    const float* out_b1 = (const float*)d_in[24];
    const float* out_W2 = (const float*)d_in[25];
    const float* out_b2 = (const float*)d_in[26];

    int N = in_sizes[0] / 12;
    int E = in_sizes[2] / 3;
    int B = out_size / 128 - N;
    const int* src = ei;
    const int* dst = ei + E;
    float* node_emb  = (float*)d_out;
    float* graph_emb = node_emb + (size_t)N * 128;

    float *p_z, *p_t1, *p_z2, *p_hcat, *p_o1;
    cudaGetSymbolAddress((void**)&p_z,    g_z);
    cudaGetSymbolAddress((void**)&p_t1,   g_t1);
    cudaGetSymbolAddress((void**)&p_z2,   g_z2);
    cudaGetSymbolAddress((void**)&p_hcat, g_hcat);
    cudaGetSymbolAddress((void**)&p_o1,   g_o1);

    // input projection + CSR build (CSR reused across all 3 layers)
    k_in_proj<<<N, 128>>>(x, in_W, in_b);
    k_zero_deg<<<(N + 255) / 256, 256>>>(N);
    k_count<<<(E + 255) / 256, 256>>>(dst, E);
    k_scan<<<1, 1024>>>(N);
    k_scatter<<<(E + 255) / 256, 256>>>(src, dst, ea, E);

    int gridM = (N + 127) / 128;
    for (int l = 0; l < 3; l++) {
        k_aggregate<<<(N * 32 + 255) / 256, 256>>>(edge_W + l * 384, edge_b + l * 128, eps, l, N);
        dim3 g1(2, gridM);
        k_sgemm<2><<<g1, 256>>>(p_z, 128, mlp_W1 + (size_t)l * 128 * 256, 256, p_t1, 256, N, 128,
                                mlp_b1 + l * 256, bn1_g + l * 256, bn1_b + l * 256,
                                bn1_rm + l * 256, bn1_rv + l * 256);
        dim3 g2(1, gridM);
        k_sgemm<2><<<g2, 256>>>(p_t1, 256, mlp_W2 + (size_t)l * 256 * 128, 128, p_z2, 128, N, 256,
                                mlp_b2 + l * 128, bn2_g + l * 128, bn2_b + l * 128,
                                bn2_rm + l * 128, bn2_rv + l * 128);
        k_ln<<<N, 128>>>(ln_g + l * 128, ln_b + l * 128, l);
    }

    dim3 go(1, gridM);
    k_sgemm<1><<<go, 256>>>(p_hcat, 512, out_W1, 128, p_o1, 128, N, 512,
                            out_b1, nullptr, nullptr, nullptr, nullptr);
    k_sgemm<0><<<go, 256>>>(p_o1, 128, out_W2, 128, node_emb, 128, N, 128,
                            out_b2, nullptr, nullptr, nullptr, nullptr);

    k_zero_pool<<<(B * 128 + 255) / 256, 256>>>(B);
    k_pool_acc<<<(N + 63) / 64, 128>>>(node_emb, batch, N);
    k_pool_fin<<<(B * 128 + 255) / 256, 256>>>(graph_emb, B);
}

// round 2
// speedup vs baseline: 1.0988x; 1.0988x over previous
#include <cuda_runtime.h>
#include <math.h>

#define MAXN 100000
#define MAXE 600000

// ---------------- scratch (no allocations allowed) ----------------
__device__ float  g_hcat[(size_t)MAXN * 512];   // h0|h1|h2|h3 concatenated per node
__device__ float  g_z   [(size_t)MAXN * 128];   // (1+eps)h + agg
__device__ float  g_t1  [(size_t)MAXN * 256];   // after mlp1
__device__ float  g_o1  [(size_t)MAXN * 128];   // relu(cat@W1+b1)
__device__ int    g_deg   [MAXN];
__device__ int    g_rowptr[MAXN + 1];
__device__ int    g_cursor[MAXN];
__device__ int    g_bsum  [256];
__device__ int    g_boff  [256];
__device__ int    g_srcs  [MAXE];
__device__ float4 g_eas   [MAXE];               // permuted edge_attr (padded)
__device__ float  g_gsum  [64 * 128];
__device__ float  g_cnt   [64];

// ---------------- input projection: h0 = x @ in_W + in_b ----------------
__global__ void k_in_proj(const float* __restrict__ x, const float* __restrict__ W,
                          const float* __restrict__ b) {
    int node = blockIdx.x;
    int c = threadIdx.x;
    __shared__ float xs[12];
    if (c < 12) xs[c] = x[node * 12 + c];
    __syncthreads();
    float a = b[c];
#pragma unroll
    for (int k = 0; k < 12; k++) a += xs[k] * W[k * 128 + c];
    g_hcat[(size_t)node * 512 + c] = a;
}

// ---------------- CSR build (by dst) ----------------
__global__ void k_zero_deg(int n) {
    int i = blockIdx.x * blockDim.x + threadIdx.x;
    if (i < n) g_deg[i] = 0;
}
__global__ void k_count(const int* __restrict__ dst, int e) {
    int i = blockIdx.x * blockDim.x + threadIdx.x;
    if (i < e) atomicAdd(&g_deg[dst[i]], 1);
}
// parallel scan, stage 1: per-block (512) local exclusive scan + block sums
__global__ void k_scan1(int n) {
    int t = threadIdx.x, b = blockIdx.x;
    int i = b * 512 + t;
    int v = (i < n) ? g_deg[i] : 0;
    int lane = t & 31, w = t >> 5;
    int x = v;
#pragma unroll
    for (int o = 1; o < 32; o <<= 1) {
        int y = __shfl_up_sync(0xFFFFFFFFu, x, o);
        if (lane >= o) x += y;
    }
    __shared__ int ws[16];
    if (lane == 31) ws[w] = x;
    __syncthreads();
    if (w == 0) {
        int y = (lane < 16) ? ws[lane] : 0;
#pragma unroll
        for (int o = 1; o < 16; o <<= 1) {
            int z = __shfl_up_sync(0xFFFFFFFFu, y, o);
            if (lane >= o) y += z;
        }
        if (lane < 16) ws[lane] = y;
    }
    __syncthreads();
    int incl = x + (w > 0 ? ws[w - 1] : 0);
    if (i < n) g_rowptr[i] = incl - v;        // block-local exclusive
    if (t == 511) g_bsum[b] = incl;           // block total
}
// stage 2: single small block scans block sums (exclusive)
__global__ void k_scan2(int nb) {
    __shared__ int s[256];
    int t = threadIdx.x;
    s[t] = (t < nb) ? g_bsum[t] : 0;
    __syncthreads();
    for (int o = 1; o < 256; o <<= 1) {
        int v = (t >= o) ? s[t - o] : 0;
        __syncthreads();
        s[t] += v;
        __syncthreads();
    }
    g_boff[t] = (t == 0) ? 0 : s[t - 1];
}
// stage 3: add block offsets, init cursor, close rowptr
__global__ void k_scan3(int n, int e) {
    int i = blockIdx.x * blockDim.x + threadIdx.x;
    if (i < n) {
        int r = g_rowptr[i] + g_boff[i >> 9];
        g_rowptr[i] = r;
        g_cursor[i] = r;
    }
    if (i == 0) g_rowptr[n] = e;
}
__global__ void k_scatter(const int* __restrict__ src, const int* __restrict__ dst,
                          const float* __restrict__ ea, int e) {
    int i = blockIdx.x * blockDim.x + threadIdx.x;
    if (i >= e) return;
    int d = dst[i];
    int p = atomicAdd(&g_cursor[d], 1);
    g_srcs[p] = src[i];
    float4 v; v.x = ea[3 * i]; v.y = ea[3 * i + 1]; v.z = ea[3 * i + 2]; v.w = 0.f;
    g_eas[p] = v;
}

// ---------------- per-layer aggregation: z = (1+eps)h + sum_in(h[src]+e) ----------------
__global__ void k_aggregate(const float* __restrict__ edgeW, const float* __restrict__ edgeb,
                            const float* __restrict__ eps, int l, int n) {
    int gid = blockIdx.x * blockDim.x + threadIdx.x;
    int node = gid >> 5, lane = gid & 31;
    if (node >= n) return;
    int c = lane * 4;
    float4 w0 = *(const float4*)(edgeW + c);
    float4 w1 = *(const float4*)(edgeW + 128 + c);
    float4 w2 = *(const float4*)(edgeW + 256 + c);
    float4 eb = *(const float4*)(edgeb + c);
    float ep = 1.f + eps[l];
    const float* hb = g_hcat + (size_t)l * 128;
    float4 hh = *(const float4*)(hb + (size_t)node * 512 + c);
    float4 acc = make_float4(ep * hh.x, ep * hh.y, ep * hh.z, ep * hh.w);
    int j0 = g_rowptr[node], j1 = g_rowptr[node + 1];
    for (int j = j0; j < j1; j++) {
        int s = g_srcs[j];
        float4 hs = *(const float4*)(hb + (size_t)s * 512 + c);
        float4 a = g_eas[j];
        acc.x += hs.x + w0.x * a.x + w1.x * a.y + w2.x * a.z + eb.x;
        acc.y += hs.y + w0.y * a.x + w1.y * a.y + w2.y * a.z + eb.y;
        acc.z += hs.z + w0.z * a.x + w1.z * a.y + w2.z * a.z + eb.z;
        acc.w += hs.w + w0.w * a.x + w1.w * a.y + w2.w * a.z + eb.w;
    }
    *(float4*)(g_z + (size_t)node * 128 + c) = acc;
}

// ---------------- SGEMM 128x128x16 tile, double-buffered, fused epilogue ----------------
// EPI: 0 = +bias, 1 = relu(+bias), 2 = relu(BN(+bias)),
//      3 = relu(BN(+bias)) + residual + LayerNorm  (requires grid.x==1, 128 cols)
template<int EPI>
__global__ __launch_bounds__(256) void k_sgemm(
    const float* __restrict__ A, int lda,
    const float* __restrict__ Bm, int ldb,
    float* __restrict__ C, int ldc,
    int M, int K,
    const float* __restrict__ bias,
    const float* __restrict__ bng, const float* __restrict__ bnb,
    const float* __restrict__ bnrm, const float* __restrict__ bnrv,
    const float* __restrict__ Res, int ldr,
    const float* __restrict__ lng, const float* __restrict__ lnb) {
    __shared__ float As[2][16][128];
    __shared__ float Bs[2][16][128];
    int tid = threadIdx.x;
    int tx = tid & 15, ty = tid >> 4;
    int rowBase = blockIdx.y * 128;
    int colBase = blockIdx.x * 128;
    float acc[8][8];
#pragma unroll
    for (int i = 0; i < 8; i++)
#pragma unroll
        for (int j = 0; j < 8; j++) acc[i][j] = 0.f;

    // tile-load index precompute (each thread handles 2 float4 per tile per operand)
    int av_r[2], av_k[2], bv_k[2], bv_c[2];
#pragma unroll
    for (int i = 0; i < 2; i++) {
        int v = tid + i * 256;
        av_r[i] = v >> 2;  av_k[i] = (v & 3) << 2;
        bv_k[i] = v >> 5;  bv_c[i] = (v & 31) << 2;
    }

    float4 aR[2], bR[2];
    // prologue: load tile 0
#pragma unroll
    for (int i = 0; i < 2; i++) {
        int gr = rowBase + av_r[i];
        aR[i] = (gr < M) ? *(const float4*)(A + (size_t)gr * lda + av_k[i])
                         : make_float4(0.f, 0.f, 0.f, 0.f);
        bR[i] = *(const float4*)(Bm + (size_t)bv_k[i] * ldb + colBase + bv_c[i]);
    }
#pragma unroll
    for (int i = 0; i < 2; i++) {
        As[0][av_k[i]][av_r[i]]     = aR[i].x;
        As[0][av_k[i] + 1][av_r[i]] = aR[i].y;
        As[0][av_k[i] + 2][av_r[i]] = aR[i].z;
        As[0][av_k[i] + 3][av_r[i]] = aR[i].w;
        *(float4*)&Bs[0][bv_k[i]][bv_c[i]] = bR[i];
    }
    __syncthreads();

    int nk = K >> 4;
    for (int t = 0; t < nk; t++) {
        int cur = t & 1;
        // prefetch next tile into registers (issues LDGs before the FMA block)
        if (t + 1 < nk) {
            int k0 = (t + 1) << 4;
#pragma unroll
            for (int i = 0; i < 2; i++) {
                int gr = rowBase + av_r[i];
                aR[i] = (gr < M) ? *(const float4*)(A + (size_t)gr * lda + k0 + av_k[i])
                                 : make_float4(0.f, 0.f, 0.f, 0.f);
                bR[i] = *(const float4*)(Bm + (size_t)(k0 + bv_k[i]) * ldb + colBase + bv_c[i]);
            }
        }
#pragma unroll
        for (int kk = 0; kk < 16; kk++) {
            float a[8], b[8];
            *(float4*)(a)     = *(const float4*)&As[cur][kk][ty * 8];
            *(float4*)(a + 4) = *(const float4*)&As[cur][kk][ty * 8 + 4];
            *(float4*)(b)     = *(const float4*)&Bs[cur][kk][tx * 8];
            *(float4*)(b + 4) = *(const float4*)&Bs[cur][kk][tx * 8 + 4];
#pragma unroll
            for (int i = 0; i < 8; i++)
#pragma unroll
                for (int j = 0; j < 8; j++)
                    acc[i][j] += a[i] * b[j];
        }
        if (t + 1 < nk) {
            int nb = cur ^ 1;
#pragma unroll
            for (int i = 0; i < 2; i++) {
                As[nb][av_k[i]][av_r[i]]     = aR[i].x;
                As[nb][av_k[i] + 1][av_r[i]] = aR[i].y;
                As[nb][av_k[i] + 2][av_r[i]] = aR[i].z;
                As[nb][av_k[i] + 3][av_r[i]] = aR[i].w;
                *(float4*)&Bs[nb][bv_k[i]][bv_c[i]] = bR[i];
            }
            __syncthreads();
        }
    }

    // epilogue scale/shift per column
    float cs[8], ct[8];
#pragma unroll
    for (int j = 0; j < 8; j++) {
        int col = colBase + tx * 8 + j;
        if (EPI >= 2) {
            float s = bng[col] * rsqrtf(bnrv[col] + 1e-5f);
            cs[j] = s; ct[j] = bnb[col] + (bias[col] - bnrm[col]) * s;
        } else { cs[j] = 1.f; ct[j] = bias[col]; }
    }

    if (EPI == 3) {
        // relu(BN) + residual, then LayerNorm across the 128 cols of each row.
        // Threads owning a row (same ty) are 16 contiguous lanes of a half-warp.
#pragma unroll
        for (int i = 0; i < 8; i++) {
            int gr = rowBase + ty * 8 + i;
            bool valid = (gr < M);
            float s = 0.f, q = 0.f;
#pragma unroll
            for (int j = 0; j < 8; j++) {
                float v = fmaxf(acc[i][j] * cs[j] + ct[j], 0.f);
                if (valid) v += Res[(size_t)gr * ldr + tx * 8 + j];
                acc[i][j] = v;
                s += v; q += v * v;
            }
#pragma unroll
            for (int o = 1; o < 16; o <<= 1) {
                s += __shfl_xor_sync(0xFFFFFFFFu, s, o);
                q += __shfl_xor_sync(0xFFFFFFFFu, q, o);
            }
            float mu = s * (1.f / 128.f);
            float var = q * (1.f / 128.f) - mu * mu;
            float r = rsqrtf(var + 1e-5f);
            if (valid) {
                float o8[8];
#pragma unroll
                for (int j = 0; j < 8; j++)
                    o8[j] = (acc[i][j] - mu) * r * lng[tx * 8 + j] + lnb[tx * 8 + j];
                *(float4*)(C + (size_t)gr * ldc + tx * 8)     = *(float4*)o8;
                *(float4*)(C + (size_t)gr * ldc + tx * 8 + 4) = *(float4*)(o8 + 4);
            }
        }
    } else {
#pragma unroll
        for (int i = 0; i < 8; i++) {
            int gr = rowBase + ty * 8 + i;
            if (gr >= M) continue;
            float o8[8];
#pragma unroll
            for (int j = 0; j < 8; j++) {
                float v = acc[i][j] * cs[j] + ct[j];
                if (EPI >= 1) v = fmaxf(v, 0.f);
                o8[j] = v;
            }
            *(float4*)(C + (size_t)gr * ldc + colBase + tx * 8)     = *(float4*)o8;
            *(float4*)(C + (size_t)gr * ldc + colBase + tx * 8 + 4) = *(float4*)(o8 + 4);
        }
    }
}

// ---------------- global mean pool ----------------
__global__ void k_zero_pool(int b) {
    int i = blockIdx.x * blockDim.x + threadIdx.x;
    if (i < b * 128) g_gsum[i] = 0.f;
    if (i < b) g_cnt[i] = 0.f;
}
__global__ void k_pool_acc(const float* __restrict__ emb, const int* __restrict__ batch, int n) {
    int c = threadIdx.x;
    int base = blockIdx.x * 64;
    float acc = 0.f, cnt = 0.f;
    int cur = -1;
    for (int i = 0; i < 64; i++) {
        int nd = base + i;
        if (nd >= n) break;
        int g = batch[nd];
        if (g != cur) {
            if (cur >= 0) {
                atomicAdd(&g_gsum[cur * 128 + c], acc);
                if (c == 0) atomicAdd(&g_cnt[cur], cnt);
            }
            cur = g; acc = 0.f; cnt = 0.f;
        }
        acc += emb[(size_t)nd * 128 + c];
        cnt += 1.f;
    }
    if (cur >= 0) {
        atomicAdd(&g_gsum[cur * 128 + c], acc);
        if (c == 0) atomicAdd(&g_cnt[cur], cnt);
    }
}
__global__ void k_pool_fin(float* __restrict__ out, int b) {
    int i = blockIdx.x * blockDim.x + threadIdx.x;
    if (i >= b * 128) return;
    out[i] = g_gsum[i] / fmaxf(g_cnt[i >> 7], 1.f);
}

// ---------------- launch ----------------
extern "C" void kernel_launch(void* const* d_in, const int* in_sizes, int n_in,
                              void* d_out, int out_size) {
    const float* x      = (const float*)d_in[0];
    const int*   ei     = (const int*)d_in[1];
    const float* ea     = (const float*)d_in[2];
    const int*   batch  = (const int*)d_in[3];
    const float* in_W   = (const float*)d_in[4];
    const float* in_b   = (const float*)d_in[5];
    const float* edge_W = (const float*)d_in[6];
    const float* edge_b = (const float*)d_in[7];
    const float* mlp_W1 = (const float*)d_in[8];
    const float* mlp_b1 = (const float*)d_in[9];
    const float* bn1_g  = (const float*)d_in[10];
    const float* bn1_b  = (const float*)d_in[11];
    const float* bn1_rm = (const float*)d_in[12];
    const float* bn1_rv = (const float*)d_in[13];
    const float* mlp_W2 = (const float*)d_in[14];
    const float* mlp_b2 = (const float*)d_in[15];
    const float* bn2_g  = (const float*)d_in[16];
    const float* bn2_b  = (const float*)d_in[17];
    const float* bn2_rm = (const float*)d_in[18];
    const float* bn2_rv = (const float*)d_in[19];
    const float* eps    = (const float*)d_in[20];
    const float* ln_g   = (const float*)d_in[21];
    const float* ln_b   = (const float*)d_in[22];
    const float* out_W1 = (const float*)d_in[23];
    const float* out_b1 = (const float*)d_in[24];
    const float* out_W2 = (const float*)d_in[25];
    const float* out_b2 = (const float*)d_in[26];

    int N = in_sizes[0] / 12;
    int E = in_sizes[2] / 3;
    int B = out_size / 128 - N;
    const int* src = ei;
    const int* dst = ei + E;
    float* node_emb  = (float*)d_out;
    float* graph_emb = node_emb + (size_t)N * 128;

    float *p_z, *p_t1, *p_hcat, *p_o1;
    cudaGetSymbolAddress((void**)&p_z,    g_z);
    cudaGetSymbolAddress((void**)&p_t1,   g_t1);
    cudaGetSymbolAddress((void**)&p_hcat, g_hcat);
    cudaGetSymbolAddress((void**)&p_o1,   g_o1);

    // input projection + CSR build (CSR reused across all 3 layers)
    k_in_proj<<<N, 128>>>(x, in_W, in_b);
    k_zero_deg<<<(N + 255) / 256, 256>>>(N);
    k_count<<<(E + 255) / 256, 256>>>(dst, E);
    int nb = (N + 511) / 512;
    k_scan1<<<nb, 512>>>(N);
    k_scan2<<<1, 256>>>(nb);
    k_scan3<<<(N + 255) / 256, 256>>>(N, E);
    k_scatter<<<(E + 255) / 256, 256>>>(src, dst, ea, E);

    int gridM = (N + 127) / 128;
    for (int l = 0; l < 3; l++) {
        k_aggregate<<<(N * 32 + 255) / 256, 256>>>(edge_W + l * 384, edge_b + l * 128, eps, l, N);
        dim3 g1(2, gridM);
        k_sgemm<2><<<g1, 256>>>(p_z, 128, mlp_W1 + (size_t)l * 128 * 256, 256, p_t1, 256, N, 128,
                                mlp_b1 + l * 256, bn1_g + l * 256, bn1_b + l * 256,
                                bn1_rm + l * 256, bn1_rv + l * 256,
                                nullptr, 0, nullptr, nullptr);
        dim3 g2(1, gridM);
        // fused: relu(BN(mlp2)) + h_l residual + LayerNorm -> h_{l+1} slice of g_hcat
        k_sgemm<3><<<g2, 256>>>(p_t1, 256, mlp_W2 + (size_t)l * 256 * 128, 128,
                                p_hcat + (l + 1) * 128, 512, N, 256,
                                mlp_b2 + l * 128, bn2_g + l * 128, bn2_b + l * 128,
                                bn2_rm + l * 128, bn2_rv + l * 128,
                                p_hcat + l * 128, 512, ln_g + l * 128, ln_b + l * 128);
    }

    dim3 go(1, gridM);
    k_sgemm<1><<<go, 256>>>(p_hcat, 512, out_W1, 128, p_o1, 128, N, 512,
                            out_b1, nullptr, nullptr, nullptr, nullptr,
                            nullptr, 0, nullptr, nullptr);
    k_sgemm<0><<<go, 256>>>(p_o1, 128, out_W2, 128, node_emb, 128, N, 128,
                            out_b2, nullptr, nullptr, nullptr, nullptr,
                            nullptr, 0, nullptr, nullptr);

    k_zero_pool<<<(B * 128 + 255) / 256, 256>>>(B);
    k_pool_acc<<<(N + 63) / 64, 128>>>(node_emb, batch, N);
    k_pool_fin<<<(B * 128 + 255) / 256, 256>>>(graph_emb, B);
}

// round 4
// speedup vs baseline: 1.7724x; 1.6130x over previous
#include <cuda_runtime.h>
#include <cuda_bf16.h>
#include <math.h>

#define MAXN 100000
#define MAXE 600000

// ---------------- scratch (no allocations allowed) ----------------
__device__ __align__(16) float  g_hcat[(size_t)MAXN * 512];   // h0|h1|h2|h3 per node
__device__ __align__(16) float  g_z   [(size_t)MAXN * 128];   // (1+eps)h + agg
__device__ __align__(16) float  g_t1  [(size_t)MAXN * 256];   // after mlp1
__device__ __align__(16) float  g_o1  [(size_t)MAXN * 128];   // relu(cat@W1+b1)
__device__ int    g_deg   [MAXN];
__device__ int    g_rowptr[MAXN + 1];
__device__ int    g_cursor[MAXN];
__device__ int    g_bsum  [256];
__device__ int    g_boff  [256];
__device__ int    g_srcs  [MAXE];
__device__ float4 g_eas   [MAXE];
__device__ float  g_gsum  [64 * 128];
__device__ float  g_cnt   [64];
// split bf16 weights, transposed to [N][K]:
// [0..98304)   mlp_W1 (3 x 256n x 128k)
// [98304..196608) mlp_W2 (3 x 128n x 256k)
// [196608..262144) out_W1 (128n x 512k)
// [262144..278528) out_W2 (128n x 128k)
__device__ __align__(16) __nv_bfloat16 g_wth[278528];
__device__ __align__(16) __nv_bfloat16 g_wtl[278528];

// ---------------- input projection ----------------
__global__ void k_in_proj(const float* __restrict__ x, const float* __restrict__ W,
                          const float* __restrict__ b) {
    int node = blockIdx.x;
    int c = threadIdx.x;
    __shared__ float xs[12];
    if (c < 12) xs[c] = x[node * 12 + c];
    __syncthreads();
    float a = b[c];
#pragma unroll
    for (int k = 0; k < 12; k++) a += xs[k] * W[k * 128 + c];
    g_hcat[(size_t)node * 512 + c] = a;
}

// ---------------- CSR build ----------------
__global__ void k_zero_deg(int n) {
    int i = blockIdx.x * blockDim.x + threadIdx.x;
    if (i < n) g_deg[i] = 0;
}
__global__ void k_count(const int* __restrict__ dst, int e) {
    int i = blockIdx.x * blockDim.x + threadIdx.x;
    if (i < e) atomicAdd(&g_deg[dst[i]], 1);
}
__global__ void k_scan1(int n) {
    int t = threadIdx.x, b = blockIdx.x;
    int i = b * 512 + t;
    int v = (i < n) ? g_deg[i] : 0;
    int lane = t & 31, w = t >> 5;
    int x = v;
#pragma unroll
    for (int o = 1; o < 32; o <<= 1) {
        int y = __shfl_up_sync(0xFFFFFFFFu, x, o);
        if (lane >= o) x += y;
    }
    __shared__ int ws[16];
    if (lane == 31) ws[w] = x;
    __syncthreads();
    if (w == 0) {
        int y = (lane < 16) ? ws[lane] : 0;
#pragma unroll
        for (int o = 1; o < 16; o <<= 1) {
            int z = __shfl_up_sync(0xFFFFFFFFu, y, o);
            if (lane >= o) y += z;
        }
        if (lane < 16) ws[lane] = y;
    }
    __syncthreads();
    int incl = x + (w > 0 ? ws[w - 1] : 0);
    if (i < n) g_rowptr[i] = incl - v;
    if (t == 511) g_bsum[b] = incl;
}
__global__ void k_scan2(int nb) {
    __shared__ int s[256];
    int t = threadIdx.x;
    s[t] = (t < nb) ? g_bsum[t] : 0;
    __syncthreads();
    for (int o = 1; o < 256; o <<= 1) {
        int v = (t >= o) ? s[t - o] : 0;
        __syncthreads();
        s[t] += v;
        __syncthreads();
    }
    g_boff[t] = (t == 0) ? 0 : s[t - 1];
}
__global__ void k_scan3(int n, int e) {
    int i = blockIdx.x * blockDim.x + threadIdx.x;
    if (i < n) {
        int r = g_rowptr[i] + g_boff[i >> 9];
        g_rowptr[i] = r;
        g_cursor[i] = r;
    }
    if (i == 0) g_rowptr[n] = e;
}
__global__ void k_scatter(const int* __restrict__ src, const int* __restrict__ dst,
                          const float* __restrict__ ea, int e) {
    int i = blockIdx.x * blockDim.x + threadIdx.x;
    if (i >= e) return;
    int d = dst[i];
    int p = atomicAdd(&g_cursor[d], 1);
    g_srcs[p] = src[i];
    float4 v; v.x = ea[3 * i]; v.y = ea[3 * i + 1]; v.z = ea[3 * i + 2]; v.w = 0.f;
    g_eas[p] = v;
}

// ---------------- aggregation ----------------
__global__ void k_aggregate(const float* __restrict__ edgeW, const float* __restrict__ edgeb,
                            const float* __restrict__ eps, int l, int n) {
    int gid = blockIdx.x * blockDim.x + threadIdx.x;
    int node = gid >> 5, lane = gid & 31;
    if (node >= n) return;
    int c = lane * 4;
    float4 w0 = *(const float4*)(edgeW + c);
    float4 w1 = *(const float4*)(edgeW + 128 + c);
    float4 w2 = *(const float4*)(edgeW + 256 + c);
    float4 eb = *(const float4*)(edgeb + c);
    float ep = 1.f + eps[l];
    const float* hb = g_hcat + (size_t)l * 128;
    float4 hh = *(const float4*)(hb + (size_t)node * 512 + c);
    float4 acc = make_float4(ep * hh.x, ep * hh.y, ep * hh.z, ep * hh.w);
    int j0 = g_rowptr[node], j1 = g_rowptr[node + 1];
    for (int j = j0; j < j1; j++) {
        int s = g_srcs[j];
        float4 hs = *(const float4*)(hb + (size_t)s * 512 + c);
        float4 a = g_eas[j];
        acc.x += hs.x + w0.x * a.x + w1.x * a.y + w2.x * a.z + eb.x;
        acc.y += hs.y + w0.y * a.x + w1.y * a.y + w2.y * a.z + eb.y;
        acc.z += hs.z + w0.z * a.x + w1.z * a.y + w2.z * a.z + eb.z;
        acc.w += hs.w + w0.w * a.x + w1.w * a.y + w2.w * a.z + eb.w;
    }
    *(float4*)(g_z + (size_t)node * 128 + c) = acc;
}

// ---------------- weight prep: transpose + bf16 hi/lo split ----------------
__global__ void k_prep(const float* __restrict__ W, int K, int N,
                       __nv_bfloat16* __restrict__ oh, __nv_bfloat16* __restrict__ ol) {
    int i = blockIdx.x * blockDim.x + threadIdx.x;
    if (i >= K * N) return;
    int k = i / N, n = i % N;
    float x = W[i];
    __nv_bfloat16 h = __float2bfloat16(x);
    __nv_bfloat16 l = __float2bfloat16(x - __bfloat162float(h));
    oh[n * K + k] = h;
    ol[n * K + k] = l;
}

// ---------------- tensor-core GEMM (bf16x3 split), fused epilogue ----------------
// C[M,N] = A[M,K] @ W[K,N], W pre-transposed/split to [N][K] bf16 hi/lo.
// EPI: 0=+bias, 1=relu(+bias), 2=relu(BN(+bias)), 3=relu(BN(+bias))+Res+LayerNorm (grid.x==1)
__device__ __forceinline__ void mma16816(float* c, const unsigned* a, const unsigned* b) {
    asm volatile(
        "mma.sync.aligned.m16n8k16.row.col.f32.bf16.bf16.f32 "
        "{%0,%1,%2,%3}, {%4,%5,%6,%7}, {%8,%9}, {%0,%1,%2,%3};\n"
        : "+f"(c[0]), "+f"(c[1]), "+f"(c[2]), "+f"(c[3])
        : "r"(a[0]), "r"(a[1]), "r"(a[2]), "r"(a[3]), "r"(b[0]), "r"(b[1]));
}
__device__ __forceinline__ void split1(float x, unsigned short& h, unsigned short& l) {
    __nv_bfloat16 hb = __float2bfloat16(x);
    __nv_bfloat16 lb = __float2bfloat16(x - __bfloat162float(hb));
    h = __bfloat16_as_ushort(hb);
    l = __bfloat16_as_ushort(lb);
}

// smem row stride in ushorts: 40 -> 80 bytes/row (multiple of 16 for uint4 stores;
// 20-bank stride, conflict-free across g=0..7 fragment rows)
#define SMS 40

template<int EPI>
__global__ __launch_bounds__(256) void k_mma(
    const float* __restrict__ A, int lda,
    const __nv_bfloat16* __restrict__ Wh, const __nv_bfloat16* __restrict__ Wl, int K,
    float* __restrict__ C, int ldc, int M,
    const float* __restrict__ bias,
    const float* __restrict__ bng, const float* __restrict__ bnb,
    const float* __restrict__ bnrm, const float* __restrict__ bnrv,
    const float* __restrict__ Res, int ldr,
    const float* __restrict__ lng, const float* __restrict__ lnb) {
    __shared__ __align__(16) unsigned short sAh[128 * SMS], sAl[128 * SMS];
    __shared__ __align__(16) unsigned short sBh[128 * SMS], sBl[128 * SMS];
    __shared__ float sRed[2][128][2];

    int tid = threadIdx.x, lane = tid & 31, wid = tid >> 5;
    int wy = wid & 3, wx = wid >> 2;          // 4x2 warp grid
    int mW = wy * 32, nW = wx * 64;
    int g = lane >> 2, qt = lane & 3;
    int rowBase = blockIdx.y * 128, colBase = blockIdx.x * 128;

    float c[2][8][4];
#pragma unroll
    for (int i = 0; i < 2; i++)
#pragma unroll
        for (int j = 0; j < 8; j++)
#pragma unroll
            for (int m = 0; m < 4; m++) c[i][j][m] = 0.f;

    // tile-load index precompute
    int a_row[4], a_k[4];
#pragma unroll
    for (int i = 0; i < 4; i++) { int v = tid + i * 256; a_row[i] = v >> 3; a_k[i] = (v & 7) * 4; }
    int b_n[2], b_k[2];
#pragma unroll
    for (int i = 0; i < 2; i++) { int v = tid + i * 256; b_n[i] = v >> 2; b_k[i] = (v & 3) * 8; }

    float4 aP[4];
    uint4 bPh[2], bPl[2];

    // prologue: load tile 0
#pragma unroll
    for (int i = 0; i < 4; i++) {
        int gr = rowBase + a_row[i];
        aP[i] = (gr < M) ? *(const float4*)(A + (size_t)gr * lda + a_k[i])
                         : make_float4(0.f, 0.f, 0.f, 0.f);
    }
#pragma unroll
    for (int i = 0; i < 2; i++) {
        size_t off = (size_t)(colBase + b_n[i]) * K + b_k[i];
        bPh[i] = *(const uint4*)(Wh + off);
        bPl[i] = *(const uint4*)(Wl + off);
    }

    int nk = K >> 5;
    for (int t = 0; t < nk; t++) {
        // store staged tile to smem
#pragma unroll
        for (int i = 0; i < 4; i++) {
            unsigned short h0, h1, h2, h3, l0, l1, l2, l3;
            split1(aP[i].x, h0, l0); split1(aP[i].y, h1, l1);
            split1(aP[i].z, h2, l2); split1(aP[i].w, h3, l3);
            uint2 uh; uh.x = (unsigned)h0 | ((unsigned)h1 << 16); uh.y = (unsigned)h2 | ((unsigned)h3 << 16);
            uint2 ul; ul.x = (unsigned)l0 | ((unsigned)l1 << 16); ul.y = (unsigned)l2 | ((unsigned)l3 << 16);
            *(uint2*)&sAh[a_row[i] * SMS + a_k[i]] = uh;
            *(uint2*)&sAl[a_row[i] * SMS + a_k[i]] = ul;
        }
#pragma unroll
        for (int i = 0; i < 2; i++) {
            *(uint4*)&sBh[b_n[i] * SMS + b_k[i]] = bPh[i];
            *(uint4*)&sBl[b_n[i] * SMS + b_k[i]] = bPl[i];
        }
        __syncthreads();

        // prefetch next tile into registers
        if (t + 1 < nk) {
            int k0 = (t + 1) << 5;
#pragma unroll
            for (int i = 0; i < 4; i++) {
                int gr = rowBase + a_row[i];
                aP[i] = (gr < M) ? *(const float4*)(A + (size_t)gr * lda + k0 + a_k[i])
                                 : make_float4(0.f, 0.f, 0.f, 0.f);
            }
#pragma unroll
            for (int i = 0; i < 2; i++) {
                size_t off = (size_t)(colBase + b_n[i]) * K + k0 + b_k[i];
                bPh[i] = *(const uint4*)(Wh + off);
                bPl[i] = *(const uint4*)(Wl + off);
            }
        }

        // compute: 2 k16 chunks
#pragma unroll
        for (int kc = 0; kc < 2; kc++) {
            int kb = kc * 16 + qt * 2;
            unsigned ah[2][4], al[2][4], bh[8][2], bl[8][2];
#pragma unroll
            for (int i = 0; i < 2; i++) {
                int r0 = (mW + i * 16 + g) * SMS;
                int r8 = r0 + 8 * SMS;
                ah[i][0] = *(const unsigned*)&sAh[r0 + kb];
                ah[i][1] = *(const unsigned*)&sAh[r8 + kb];
                ah[i][2] = *(const unsigned*)&sAh[r0 + kb + 8];
                ah[i][3] = *(const unsigned*)&sAh[r8 + kb + 8];
                al[i][0] = *(const unsigned*)&sAl[r0 + kb];
                al[i][1] = *(const unsigned*)&sAl[r8 + kb];
                al[i][2] = *(const unsigned*)&sAl[r0 + kb + 8];
                al[i][3] = *(const unsigned*)&sAl[r8 + kb + 8];
            }
#pragma unroll
            for (int j = 0; j < 8; j++) {
                int n0 = (nW + j * 8 + g) * SMS;
                bh[j][0] = *(const unsigned*)&sBh[n0 + kb];
                bh[j][1] = *(const unsigned*)&sBh[n0 + kb + 8];
                bl[j][0] = *(const unsigned*)&sBl[n0 + kb];
                bl[j][1] = *(const unsigned*)&sBl[n0 + kb + 8];
            }
#pragma unroll
            for (int i = 0; i < 2; i++)
#pragma unroll
                for (int j = 0; j < 8; j++) {
                    mma16816(c[i][j], ah[i], bh[j]);
                    mma16816(c[i][j], ah[i], bl[j]);
                    mma16816(c[i][j], al[i], bh[j]);
                }
        }
        if (t + 1 < nk) __syncthreads();
    }

    // epilogue: per-column scale/shift
    float cs[8][2], ct[8][2];
#pragma unroll
    for (int j = 0; j < 8; j++) {
#pragma unroll
        for (int h = 0; h < 2; h++) {
            int col = colBase + nW + j * 8 + qt * 2 + h;
            if (EPI >= 2) {
                float s = bng[col] * rsqrtf(bnrv[col] + 1e-5f);
                cs[j][h] = s; ct[j][h] = bnb[col] + (bias[col] - bnrm[col]) * s;
            } else { cs[j][h] = 1.f; ct[j][h] = bias[col]; }
        }
    }

    if (EPI == 3) {
        float s[2][2], q[2][2];
#pragma unroll
        for (int i = 0; i < 2; i++) { s[i][0] = s[i][1] = 0.f; q[i][0] = q[i][1] = 0.f; }
#pragma unroll
        for (int i = 0; i < 2; i++) {
            int r1 = rowBase + mW + i * 16 + g, r2 = r1 + 8;
#pragma unroll
            for (int j = 0; j < 8; j++) {
                int colL = nW + j * 8 + qt * 2;
                float2 res1 = make_float2(0.f, 0.f), res2 = make_float2(0.f, 0.f);
                if (r1 < M) res1 = *(const float2*)(Res + (size_t)r1 * ldr + colL);
                if (r2 < M) res2 = *(const float2*)(Res + (size_t)r2 * ldr + colL);
                float v0 = fmaxf(c[i][j][0] * cs[j][0] + ct[j][0], 0.f) + res1.x;
                float v1 = fmaxf(c[i][j][1] * cs[j][1] + ct[j][1], 0.f) + res1.y;
                float v2 = fmaxf(c[i][j][2] * cs[j][0] + ct[j][0], 0.f) + res2.x;
                float v3 = fmaxf(c[i][j][3] * cs[j][1] + ct[j][1], 0.f) + res2.y;
                c[i][j][0] = v0; c[i][j][1] = v1; c[i][j][2] = v2; c[i][j][3] = v3;
                s[i][0] += v0 + v1; q[i][0] += v0 * v0 + v1 * v1;
                s[i][1] += v2 + v3; q[i][1] += v2 * v2 + v3 * v3;
            }
        }
#pragma unroll
        for (int i = 0; i < 2; i++)
#pragma unroll
            for (int h = 0; h < 2; h++) {
                s[i][h] += __shfl_xor_sync(0xFFFFFFFFu, s[i][h], 1);
                s[i][h] += __shfl_xor_sync(0xFFFFFFFFu, s[i][h], 2);
                q[i][h] += __shfl_xor_sync(0xFFFFFFFFu, q[i][h], 1);
                q[i][h] += __shfl_xor_sync(0xFFFFFFFFu, q[i][h], 2);
            }
        if (qt == 0) {
#pragma unroll
            for (int i = 0; i < 2; i++)
#pragma unroll
                for (int h = 0; h < 2; h++) {
                    int lr = mW + i * 16 + g + h * 8;
                    sRed[0][lr][wx] = s[i][h];
                    sRed[1][lr][wx] = q[i][h];
                }
        }
        __syncthreads();
#pragma unroll
        for (int i = 0; i < 2; i++)
#pragma unroll
            for (int h = 0; h < 2; h++) {
                int lr = mW + i * 16 + g + h * 8;
                int gr = rowBase + lr;
                float ts = sRed[0][lr][0] + sRed[0][lr][1];
                float tq = sRed[1][lr][0] + sRed[1][lr][1];
                float mu = ts * (1.f / 128.f);
                float var = tq * (1.f / 128.f) - mu * mu;
                float rr = rsqrtf(var + 1e-5f);
                if (gr < M) {
#pragma unroll
                    for (int j = 0; j < 8; j++) {
                        int colL = nW + j * 8 + qt * 2;
                        float2 o;
                        o.x = (c[i][j][h * 2]     - mu) * rr * lng[colL]     + lnb[colL];
                        o.y = (c[i][j][h * 2 + 1] - mu) * rr * lng[colL + 1] + lnb[colL + 1];
                        *(float2*)(C + (size_t)gr * ldc + colL) = o;
                    }
                }
            }
    } else {
#pragma unroll
        for (int i = 0; i < 2; i++) {
            int r1 = rowBase + mW + i * 16 + g, r2 = r1 + 8;
#pragma unroll
            for (int j = 0; j < 8; j++) {
                int col = colBase + nW + j * 8 + qt * 2;
                float o0 = c[i][j][0] * cs[j][0] + ct[j][0];
                float o1 = c[i][j][1] * cs[j][1] + ct[j][1];
                float o2 = c[i][j][2] * cs[j][0] + ct[j][0];
                float o3 = c[i][j][3] * cs[j][1] + ct[j][1];
                if (EPI >= 1) {
                    o0 = fmaxf(o0, 0.f); o1 = fmaxf(o1, 0.f);
                    o2 = fmaxf(o2, 0.f); o3 = fmaxf(o3, 0.f);
                }
                if (r1 < M) { float2 o; o.x = o0; o.y = o1; *(float2*)(C + (size_t)r1 * ldc + col) = o; }
                if (r2 < M) { float2 o; o.x = o2; o.y = o3; *(float2*)(C + (size_t)r2 * ldc + col) = o; }
            }
        }
    }
}

// ---------------- global mean pool ----------------
__global__ void k_zero_pool(int b) {
    int i = blockIdx.x * blockDim.x + threadIdx.x;
    if (i < b * 128) g_gsum[i] = 0.f;
    if (i < b) g_cnt[i] = 0.f;
}
__global__ void k_pool_acc(const float* __restrict__ emb, const int* __restrict__ batch, int n) {
    int c = threadIdx.x;
    int base = blockIdx.x * 64;
    float acc = 0.f, cnt = 0.f;
    int cur = -1;
    for (int i = 0; i < 64; i++) {
        int nd = base + i;
        if (nd >= n) break;
        int g = batch[nd];
        if (g != cur) {
            if (cur >= 0) {
                atomicAdd(&g_gsum[cur * 128 + c], acc);
                if (c == 0) atomicAdd(&g_cnt[cur], cnt);
            }
            cur = g; acc = 0.f; cnt = 0.f;
        }
        acc += emb[(size_t)nd * 128 + c];
        cnt += 1.f;
    }
    if (cur >= 0) {
        atomicAdd(&g_gsum[cur * 128 + c], acc);
        if (c == 0) atomicAdd(&g_cnt[cur], cnt);
    }
}
__global__ void k_pool_fin(float* __restrict__ out, int b) {
    int i = blockIdx.x * blockDim.x + threadIdx.x;
    if (i >= b * 128) return;
    out[i] = g_gsum[i] / fmaxf(g_cnt[i >> 7], 1.f);
}

// ---------------- launch ----------------
extern "C" void kernel_launch(void* const* d_in, const int* in_sizes, int n_in,
                              void* d_out, int out_size) {
    const float* x      = (const float*)d_in[0];
    const int*   ei     = (const int*)d_in[1];
    const float* ea     = (const float*)d_in[2];
    const int*   batch  = (const int*)d_in[3];
    const float* in_W   = (const float*)d_in[4];
    const float* in_b   = (const float*)d_in[5];
    const float* edge_W = (const float*)d_in[6];
    const float* edge_b = (const float*)d_in[7];
    const float* mlp_W1 = (const float*)d_in[8];
    const float* mlp_b1 = (const float*)d_in[9];
    const float* bn1_g  = (const float*)d_in[10];
    const float* bn1_b  = (const float*)d_in[11];
    const float* bn1_rm = (const float*)d_in[12];
    const float* bn1_rv = (const float*)d_in[13];
    const float* mlp_W2 = (const float*)d_in[14];
    const float* mlp_b2 = (const float*)d_in[15];
    const float* bn2_g  = (const float*)d_in[16];
    const float* bn2_b  = (const float*)d_in[17];
    const float* bn2_rm = (const float*)d_in[18];
    const float* bn2_rv = (const float*)d_in[19];
    const float* eps    = (const float*)d_in[20];
    const float* ln_g   = (const float*)d_in[21];
    const float* ln_b   = (const float*)d_in[22];
    const float* out_W1 = (const float*)d_in[23];
    const float* out_b1 = (const float*)d_in[24];
    const float* out_W2 = (const float*)d_in[25];
    const float* out_b2 = (const float*)d_in[26];

    int N = in_sizes[0] / 12;
    int E = in_sizes[2] / 3;
    int B = out_size / 128 - N;
    const int* src = ei;
    const int* dst = ei + E;
    float* node_emb  = (float*)d_out;
    float* graph_emb = node_emb + (size_t)N * 128;

    float *p_z, *p_t1, *p_hcat, *p_o1;
    __nv_bfloat16 *p_wh, *p_wl;
    cudaGetSymbolAddress((void**)&p_z,    g_z);
    cudaGetSymbolAddress((void**)&p_t1,   g_t1);
    cudaGetSymbolAddress((void**)&p_hcat, g_hcat);
    cudaGetSymbolAddress((void**)&p_o1,   g_o1);
    cudaGetSymbolAddress((void**)&p_wh,   g_wth);
    cudaGetSymbolAddress((void**)&p_wl,   g_wtl);

    // weight prep: transpose + bf16 hi/lo split (cheap, once per launch)
    for (int l = 0; l < 3; l++) {
        k_prep<<<(128 * 256 + 255) / 256, 256>>>(mlp_W1 + (size_t)l * 32768, 128, 256,
                                                 p_wh + l * 32768, p_wl + l * 32768);
        k_prep<<<(256 * 128 + 255) / 256, 256>>>(mlp_W2 + (size_t)l * 32768, 256, 128,
                                                 p_wh + 98304 + l * 32768, p_wl + 98304 + l * 32768);
    }
    k_prep<<<(512 * 128 + 255) / 256, 256>>>(out_W1, 512, 128, p_wh + 196608, p_wl + 196608);
    k_prep<<<(128 * 128 + 255) / 256, 256>>>(out_W2, 128, 128, p_wh + 262144, p_wl + 262144);

    // input projection + CSR build
    k_in_proj<<<N, 128>>>(x, in_W, in_b);
    k_zero_deg<<<(N + 255) / 256, 256>>>(N);
    k_count<<<(E + 255) / 256, 256>>>(dst, E);
    int nb = (N + 511) / 512;
    k_scan1<<<nb, 512>>>(N);
    k_scan2<<<1, 256>>>(nb);
    k_scan3<<<(N + 255) / 256, 256>>>(N, E);
    k_scatter<<<(E + 255) / 256, 256>>>(src, dst, ea, E);

    int gridM = (N + 127) / 128;
    for (int l = 0; l < 3; l++) {
        k_aggregate<<<(N * 32 + 255) / 256, 256>>>(edge_W + l * 384, edge_b + l * 128, eps, l, N);
        dim3 g1(2, gridM);
        k_mma<2><<<g1, 256>>>(p_z, 128, p_wh + l * 32768, p_wl + l * 32768, 128,
                              p_t1, 256, N,
                              mlp_b1 + l * 256, bn1_g + l * 256, bn1_b + l * 256,
                              bn1_rm + l * 256, bn1_rv + l * 256,
                              nullptr, 0, nullptr, nullptr);
        dim3 g2(1, gridM);
        k_mma<3><<<g2, 256>>>(p_t1, 256, p_wh + 98304 + l * 32768, p_wl + 98304 + l * 32768, 256,
                              p_hcat + (l + 1) * 128, 512, N,
                              mlp_b2 + l * 128, bn2_g + l * 128, bn2_b + l * 128,
                              bn2_rm + l * 128, bn2_rv + l * 128,
                              p_hcat + l * 128, 512, ln_g + l * 128, ln_b + l * 128);
    }

    dim3 go(1, gridM);
    k_mma<1><<<go, 256>>>(p_hcat, 512, p_wh + 196608, p_wl + 196608, 512,
                          p_o1, 128, N,
                          out_b1, nullptr, nullptr, nullptr, nullptr,
                          nullptr, 0, nullptr, nullptr);
    k_mma<0><<<go, 256>>>(p_o1, 128, p_wh + 262144, p_wl + 262144, 128,
                          node_emb, 128, N,
                          out_b2, nullptr, nullptr, nullptr, nullptr,
                          nullptr, 0, nullptr, nullptr);

    k_zero_pool<<<(B * 128 + 255) / 256, 256>>>(B);
    k_pool_acc<<<(N + 63) / 64, 128>>>(node_emb, batch, N);
    k_pool_fin<<<(B * 128 + 255) / 256, 256>>>(graph_emb, B);
}

// round 6
// speedup vs baseline: 1.8484x; 1.0429x over previous
#include <cuda_runtime.h>
#include <cuda_bf16.h>
#include <cstdint>
#include <math.h>

#define MAXN 100000
#define MAXE 600000

// ---------------- scratch (no allocations allowed) ----------------
__device__ __align__(16) float  g_hcat[(size_t)MAXN * 512];   // h0|h1|h2|h3 per node
__device__ __align__(16) float  g_z   [(size_t)MAXN * 128];
__device__ __align__(16) float  g_t1  [(size_t)MAXN * 256];
__device__ __align__(16) float  g_o1  [(size_t)MAXN * 128];
__device__ int    g_deg   [MAXN];
__device__ int    g_rowptr[MAXN + 1];
__device__ int    g_cursor[MAXN];
__device__ int    g_bsum  [256];
__device__ int    g_boff  [256];
__device__ int    g_srcs  [MAXE];
__device__ float4 g_eas   [MAXE];
__device__ float  g_gsum  [64 * 128];
__device__ float  g_cnt   [64];
// split bf16 weights, transposed to [N][K]
__device__ __align__(16) __nv_bfloat16 g_wth[278528];
__device__ __align__(16) __nv_bfloat16 g_wtl[278528];

// ---------------- input projection ----------------
__global__ void k_in_proj(const float* __restrict__ x, const float* __restrict__ W,
                          const float* __restrict__ b) {
    int node = blockIdx.x;
    int c = threadIdx.x;
    __shared__ float xs[12];
    if (c < 12) xs[c] = x[node * 12 + c];
    __syncthreads();
    float a = b[c];
#pragma unroll
    for (int k = 0; k < 12; k++) a += xs[k] * W[k * 128 + c];
    g_hcat[(size_t)node * 512 + c] = a;
}

// ---------------- CSR build ----------------
__global__ void k_zero_deg(int n) {
    int i = blockIdx.x * blockDim.x + threadIdx.x;
    if (i < n) g_deg[i] = 0;
}
__global__ void k_count(const int* __restrict__ dst, int e) {
    int i = blockIdx.x * blockDim.x + threadIdx.x;
    if (i < e) atomicAdd(&g_deg[dst[i]], 1);
}
__global__ void k_scan1(int n) {
    int t = threadIdx.x, b = blockIdx.x;
    int i = b * 512 + t;
    int v = (i < n) ? g_deg[i] : 0;
    int lane = t & 31, w = t >> 5;
    int x = v;
#pragma unroll
    for (int o = 1; o < 32; o <<= 1) {
        int y = __shfl_up_sync(0xFFFFFFFFu, x, o);
        if (lane >= o) x += y;
    }
    __shared__ int ws[16];
    if (lane == 31) ws[w] = x;
    __syncthreads();
    if (w == 0) {
        int y = (lane < 16) ? ws[lane] : 0;
#pragma unroll
        for (int o = 1; o < 16; o <<= 1) {
            int z = __shfl_up_sync(0xFFFFFFFFu, y, o);
            if (lane >= o) y += z;
        }
        if (lane < 16) ws[lane] = y;
    }
    __syncthreads();
    int incl = x + (w > 0 ? ws[w - 1] : 0);
    if (i < n) g_rowptr[i] = incl - v;
    if (t == 511) g_bsum[b] = incl;
}
__global__ void k_scan2(int nb) {
    __shared__ int s[256];
    int t = threadIdx.x;
    s[t] = (t < nb) ? g_bsum[t] : 0;
    __syncthreads();
    for (int o = 1; o < 256; o <<= 1) {
        int v = (t >= o) ? s[t - o] : 0;
        __syncthreads();
        s[t] += v;
        __syncthreads();
    }
    g_boff[t] = (t == 0) ? 0 : s[t - 1];
}
__global__ void k_scan3(int n, int e) {
    int i = blockIdx.x * blockDim.x + threadIdx.x;
    if (i < n) {
        int r = g_rowptr[i] + g_boff[i >> 9];
        g_rowptr[i] = r;
        g_cursor[i] = r;
    }
    if (i == 0) g_rowptr[n] = e;
}
__global__ void k_scatter(const int* __restrict__ src, const int* __restrict__ dst,
                          const float* __restrict__ ea, int e) {
    int i = blockIdx.x * blockDim.x + threadIdx.x;
    if (i >= e) return;
    int d = dst[i];
    int p = atomicAdd(&g_cursor[d], 1);
    g_srcs[p] = src[i];
    float4 v; v.x = ea[3 * i]; v.y = ea[3 * i + 1]; v.z = ea[3 * i + 2]; v.w = 0.f;
    g_eas[p] = v;
}

// ---------------- aggregation ----------------
__global__ void k_aggregate(const float* __restrict__ edgeW, const float* __restrict__ edgeb,
                            const float* __restrict__ eps, int l, int n) {
    int gid = blockIdx.x * blockDim.x + threadIdx.x;
    int node = gid >> 5, lane = gid & 31;
    if (node >= n) return;
    int c = lane * 4;
    float4 w0 = *(const float4*)(edgeW + c);
    float4 w1 = *(const float4*)(edgeW + 128 + c);
    float4 w2 = *(const float4*)(edgeW + 256 + c);
    float4 eb = *(const float4*)(edgeb + c);
    float ep = 1.f + eps[l];
    const float* hb = g_hcat + (size_t)l * 128;
    float4 hh = *(const float4*)(hb + (size_t)node * 512 + c);
    float4 acc = make_float4(ep * hh.x, ep * hh.y, ep * hh.z, ep * hh.w);
    int j0 = g_rowptr[node], j1 = g_rowptr[node + 1];
    for (int j = j0; j < j1; j++) {
        int s = g_srcs[j];
        float4 hs = *(const float4*)(hb + (size_t)s * 512 + c);
        float4 a = g_eas[j];
        acc.x += hs.x + w0.x * a.x + w1.x * a.y + w2.x * a.z + eb.x;
        acc.y += hs.y + w0.y * a.x + w1.y * a.y + w2.y * a.z + eb.y;
        acc.z += hs.z + w0.z * a.x + w1.z * a.y + w2.z * a.z + eb.z;
        acc.w += hs.w + w0.w * a.x + w1.w * a.y + w2.w * a.z + eb.w;
    }
    *(float4*)(g_z + (size_t)node * 128 + c) = acc;
}

// ---------------- weight prep: transpose + bf16 hi/lo split ----------------
__global__ void k_prep(const float* __restrict__ W, int K, int N,
                       __nv_bfloat16* __restrict__ oh, __nv_bfloat16* __restrict__ ol) {
    int i = blockIdx.x * blockDim.x + threadIdx.x;
    if (i >= K * N) return;
    int k = i / N, n = i % N;
    float x = W[i];
    __nv_bfloat16 h = __float2bfloat16(x);
    __nv_bfloat16 l = __float2bfloat16(x - __bfloat162float(h));
    oh[n * K + k] = h;
    ol[n * K + k] = l;
}

// ---------------- tensor-core GEMM (bf16x3 split, ldmatrix), fused epilogue ----------------
__device__ __forceinline__ void mma16816(float* c, const unsigned* a, const unsigned* b) {
    asm volatile(
        "mma.sync.aligned.m16n8k16.row.col.f32.bf16.bf16.f32 "
        "{%0,%1,%2,%3}, {%4,%5,%6,%7}, {%8,%9}, {%0,%1,%2,%3};\n"
        : "+f"(c[0]), "+f"(c[1]), "+f"(c[2]), "+f"(c[3])
        : "r"(a[0]), "r"(a[1]), "r"(a[2]), "r"(a[3]), "r"(b[0]), "r"(b[1]));
}
__device__ __forceinline__ void ldm_x4(unsigned* r, uint32_t a) {
    asm volatile("ldmatrix.sync.aligned.m8n8.x4.shared.b16 {%0,%1,%2,%3}, [%4];"
        : "=r"(r[0]), "=r"(r[1]), "=r"(r[2]), "=r"(r[3]) : "r"(a));
}
__device__ __forceinline__ uint32_t smem_u32(const void* p) {
    uint32_t a;
    asm("{ .reg .u64 t; cvta.to.shared.u64 t, %1; cvt.u32.u64 %0, t; }" : "=r"(a) : "l"(p));
    return a;
}
__device__ __forceinline__ void split1(float x, unsigned short& h, unsigned short& l) {
    __nv_bfloat16 hb = __float2bfloat16(x);
    __nv_bfloat16 lb = __float2bfloat16(x - __bfloat162float(hb));
    h = __bfloat16_as_ushort(hb);
    l = __bfloat16_as_ushort(lb);
}

// smem row stride in ushorts: 40 -> 80 B/row (16B-aligned rows, conflict-free ldmatrix)
#define SMS 40

template<int EPI>
__global__ __launch_bounds__(256) void k_mma(
    const float* __restrict__ A, int lda,
    const __nv_bfloat16* __restrict__ Wh, const __nv_bfloat16* __restrict__ Wl, int K,
    float* __restrict__ C, int ldc, int M,
    const float* __restrict__ bias,
    const float* __restrict__ bng, const float* __restrict__ bnb,
    const float* __restrict__ bnrm, const float* __restrict__ bnrv,
    const float* __restrict__ Res, int ldr,
    const float* __restrict__ lng, const float* __restrict__ lnb) {
    __shared__ __align__(16) unsigned short sAh[128 * SMS], sAl[128 * SMS];
    __shared__ __align__(16) unsigned short sBh[128 * SMS], sBl[128 * SMS];
    __shared__ float sRed[2][128][2];

    int tid = threadIdx.x, lane = tid & 31, wid = tid >> 5;
    int wy = wid & 3, wx = wid >> 2;          // 4x2 warp grid
    int mW = wy * 32, nW = wx * 64;
    int g = lane >> 2, qt = lane & 3;
    int rowBase = blockIdx.y * 128, colBase = blockIdx.x * 128;

    float c[2][8][4];
#pragma unroll
    for (int i = 0; i < 2; i++)
#pragma unroll
        for (int j = 0; j < 8; j++)
#pragma unroll
            for (int m = 0; m < 4; m++) c[i][j][m] = 0.f;

    // ldmatrix base addresses (bytes)
    uint32_t aOff = (uint32_t)((mW + (lane & 15)) * SMS + ((lane >> 4) << 3)) * 2;
    uint32_t bOff = (uint32_t)((nW + ((lane >> 4) << 3) + (lane & 7)) * SMS + (((lane >> 3) & 1) << 3)) * 2;
    uint32_t sAhB = smem_u32(sAh) + aOff, sAlB = smem_u32(sAl) + aOff;
    uint32_t sBhB = smem_u32(sBh) + bOff, sBlB = smem_u32(sBl) + bOff;

    // tile-load index precompute
    int a_row[4], a_k[4];
#pragma unroll
    for (int i = 0; i < 4; i++) { int v = tid + i * 256; a_row[i] = v >> 3; a_k[i] = (v & 7) * 4; }
    int b_n[2], b_k[2];
#pragma unroll
    for (int i = 0; i < 2; i++) { int v = tid + i * 256; b_n[i] = v >> 2; b_k[i] = (v & 3) * 8; }

    float4 aP[4];
    uint4 bPh[2], bPl[2];

    // prologue: load tile 0
#pragma unroll
    for (int i = 0; i < 4; i++) {
        int gr = rowBase + a_row[i];
        aP[i] = (gr < M) ? *(const float4*)(A + (size_t)gr * lda + a_k[i])
                         : make_float4(0.f, 0.f, 0.f, 0.f);
    }
#pragma unroll
    for (int i = 0; i < 2; i++) {
        size_t off = (size_t)(colBase + b_n[i]) * K + b_k[i];
        bPh[i] = *(const uint4*)(Wh + off);
        bPl[i] = *(const uint4*)(Wl + off);
    }

    int nk = K >> 5;
    for (int t = 0; t < nk; t++) {
        // store staged tile to smem
#pragma unroll
        for (int i = 0; i < 4; i++) {
            unsigned short h0, h1, h2, h3, l0, l1, l2, l3;
            split1(aP[i].x, h0, l0); split1(aP[i].y, h1, l1);
            split1(aP[i].z, h2, l2); split1(aP[i].w, h3, l3);
            uint2 uh; uh.x = (unsigned)h0 | ((unsigned)h1 << 16); uh.y = (unsigned)h2 | ((unsigned)h3 << 16);
            uint2 ul; ul.x = (unsigned)l0 | ((unsigned)l1 << 16); ul.y = (unsigned)l2 | ((unsigned)l3 << 16);
            *(uint2*)&sAh[a_row[i] * SMS + a_k[i]] = uh;
            *(uint2*)&sAl[a_row[i] * SMS + a_k[i]] = ul;
        }
#pragma unroll
        for (int i = 0; i < 2; i++) {
            *(uint4*)&sBh[b_n[i] * SMS + b_k[i]] = bPh[i];
            *(uint4*)&sBl[b_n[i] * SMS + b_k[i]] = bPl[i];
        }
        __syncthreads();

        // prefetch next tile into registers
        if (t + 1 < nk) {
            int k0 = (t + 1) << 5;
#pragma unroll
            for (int i = 0; i < 4; i++) {
                int gr = rowBase + a_row[i];
                aP[i] = (gr < M) ? *(const float4*)(A + (size_t)gr * lda + k0 + a_k[i])
                                 : make_float4(0.f, 0.f, 0.f, 0.f);
            }
#pragma unroll
            for (int i = 0; i < 2; i++) {
                size_t off = (size_t)(colBase + b_n[i]) * K + k0 + b_k[i];
                bPh[i] = *(const uint4*)(Wh + off);
                bPl[i] = *(const uint4*)(Wl + off);
            }
        }

        // compute: 2 k16 chunks, fragments via ldmatrix.x4
#pragma unroll
        for (int kc = 0; kc < 2; kc++) {
            uint32_t kByte = (uint32_t)(kc * 16) * 2;
            unsigned ah[2][4], al[2][4], bh[8][2], bl[8][2];
#pragma unroll
            for (int i = 0; i < 2; i++) {
                uint32_t rb = (uint32_t)(i * 16 * SMS) * 2 + kByte;
                ldm_x4(ah[i], sAhB + rb);
                ldm_x4(al[i], sAlB + rb);
            }
#pragma unroll
            for (int j2 = 0; j2 < 4; j2++) {
                uint32_t rb = (uint32_t)(j2 * 16 * SMS) * 2 + kByte;
                ldm_x4(&bh[j2 * 2][0], sBhB + rb);
                ldm_x4(&bl[j2 * 2][0], sBlB + rb);
            }
#pragma unroll
            for (int i = 0; i < 2; i++)
#pragma unroll
                for (int j = 0; j < 8; j++) {
                    mma16816(c[i][j], ah[i], bh[j]);
                    mma16816(c[i][j], ah[i], bl[j]);
                    mma16816(c[i][j], al[i], bh[j]);
                }
        }
        if (t + 1 < nk) __syncthreads();
    }

    // epilogue: per-column scale/shift
    float cs[8][2], ct[8][2];
#pragma unroll
    for (int j = 0; j < 8; j++) {
#pragma unroll
        for (int h = 0; h < 2; h++) {
            int col = colBase + nW + j * 8 + qt * 2 + h;
            if (EPI >= 2) {
                float s = bng[col] * rsqrtf(bnrv[col] + 1e-5f);
                cs[j][h] = s; ct[j][h] = bnb[col] + (bias[col] - bnrm[col]) * s;
            } else { cs[j][h] = 1.f; ct[j][h] = bias[col]; }
        }
    }

    if (EPI == 3) {
        float s[2][2], q[2][2];
#pragma unroll
        for (int i = 0; i < 2; i++) { s[i][0] = s[i][1] = 0.f; q[i][0] = q[i][1] = 0.f; }
#pragma unroll
        for (int i = 0; i < 2; i++) {
            int r1 = rowBase + mW + i * 16 + g, r2 = r1 + 8;
#pragma unroll
            for (int j = 0; j < 8; j++) {
                int colL = nW + j * 8 + qt * 2;
                float2 res1 = make_float2(0.f, 0.f), res2 = make_float2(0.f, 0.f);
                if (r1 < M) res1 = *(const float2*)(Res + (size_t)r1 * ldr + colL);
                if (r2 < M) res2 = *(const float2*)(Res + (size_t)r2 * ldr + colL);
                float v0 = fmaxf(c[i][j][0] * cs[j][0] + ct[j][0], 0.f) + res1.x;
                float v1 = fmaxf(c[i][j][1] * cs[j][1] + ct[j][1], 0.f) + res1.y;
                float v2 = fmaxf(c[i][j][2] * cs[j][0] + ct[j][0], 0.f) + res2.x;
                float v3 = fmaxf(c[i][j][3] * cs[j][1] + ct[j][1], 0.f) + res2.y;
                c[i][j][0] = v0; c[i][j][1] = v1; c[i][j][2] = v2; c[i][j][3] = v3;
                s[i][0] += v0 + v1; q[i][0] += v0 * v0 + v1 * v1;
                s[i][1] += v2 + v3; q[i][1] += v2 * v2 + v3 * v3;
            }
        }
#pragma unroll
        for (int i = 0; i < 2; i++)
#pragma unroll
            for (int h = 0; h < 2; h++) {
                s[i][h] += __shfl_xor_sync(0xFFFFFFFFu, s[i][h], 1);
                s[i][h] += __shfl_xor_sync(0xFFFFFFFFu, s[i][h], 2);
                q[i][h] += __shfl_xor_sync(0xFFFFFFFFu, q[i][h], 1);
                q[i][h] += __shfl_xor_sync(0xFFFFFFFFu, q[i][h], 2);
            }
        if (qt == 0) {
#pragma unroll
            for (int i = 0; i < 2; i++)
#pragma unroll
                for (int h = 0; h < 2; h++) {
                    int lr = mW + i * 16 + g + h * 8;
                    sRed[0][lr][wx] = s[i][h];
                    sRed[1][lr][wx] = q[i][h];
                }
        }
        __syncthreads();
#pragma unroll
        for (int i = 0; i < 2; i++)
#pragma unroll
            for (int h = 0; h < 2; h++) {
                int lr = mW + i * 16 + g + h * 8;
                int gr = rowBase + lr;
                float ts = sRed[0][lr][0] + sRed[0][lr][1];
                float tq = sRed[1][lr][0] + sRed[1][lr][1];
                float mu = ts * (1.f / 128.f);
                float var = tq * (1.f / 128.f) - mu * mu;
                float rr = rsqrtf(var + 1e-5f);
                if (gr < M) {
#pragma unroll
                    for (int j = 0; j < 8; j++) {
                        int colL = nW + j * 8 + qt * 2;
                        float2 o;
                        o.x = (c[i][j][h * 2]     - mu) * rr * lng[colL]     + lnb[colL];
                        o.y = (c[i][j][h * 2 + 1] - mu) * rr * lng[colL + 1] + lnb[colL + 1];
                        *(float2*)(C + (size_t)gr * ldc + colL) = o;
                    }
                }
            }
    } else {
#pragma unroll
        for (int i = 0; i < 2; i++) {
            int r1 = rowBase + mW + i * 16 + g, r2 = r1 + 8;
#pragma unroll
            for (int j = 0; j < 8; j++) {
                int col = colBase + nW + j * 8 + qt * 2;
                float o0 = c[i][j][0] * cs[j][0] + ct[j][0];
                float o1 = c[i][j][1] * cs[j][1] + ct[j][1];
                float o2 = c[i][j][2] * cs[j][0] + ct[j][0];
                float o3 = c[i][j][3] * cs[j][1] + ct[j][1];
                if (EPI >= 1) {
                    o0 = fmaxf(o0, 0.f); o1 = fmaxf(o1, 0.f);
                    o2 = fmaxf(o2, 0.f); o3 = fmaxf(o3, 0.f);
                }
                if (r1 < M) { float2 o; o.x = o0; o.y = o1; *(float2*)(C + (size_t)r1 * ldc + col) = o; }
                if (r2 < M) { float2 o; o.x = o2; o.y = o3; *(float2*)(C + (size_t)r2 * ldc + col) = o; }
            }
        }
    }
}

// ---------------- global mean pool ----------------
__global__ void k_zero_pool(int b) {
    int i = blockIdx.x * blockDim.x + threadIdx.x;
    if (i < b * 128) g_gsum[i] = 0.f;
    if (i < b) g_cnt[i] = 0.f;
}
__global__ void k_pool_acc(const float* __restrict__ emb, const int* __restrict__ batch, int n) {
    int c = threadIdx.x;
    int base = blockIdx.x * 64;
    float acc = 0.f, cnt = 0.f;
    int cur = -1;
    for (int i = 0; i < 64; i++) {
        int nd = base + i;
        if (nd >= n) break;
        int g = batch[nd];
        if (g != cur) {
            if (cur >= 0) {
                atomicAdd(&g_gsum[cur * 128 + c], acc);
                if (c == 0) atomicAdd(&g_cnt[cur], cnt);
            }
            cur = g; acc = 0.f; cnt = 0.f;
        }
        acc += emb[(size_t)nd * 128 + c];
        cnt += 1.f;
    }
    if (cur >= 0) {
        atomicAdd(&g_gsum[cur * 128 + c], acc);
        if (c == 0) atomicAdd(&g_cnt[cur], cnt);
    }
}
__global__ void k_pool_fin(float* __restrict__ out, int b) {
    int i = blockIdx.x * blockDim.x + threadIdx.x;
    if (i >= b * 128) return;
    out[i] = g_gsum[i] / fmaxf(g_cnt[i >> 7], 1.f);
}

// ---------------- launch ----------------
extern "C" void kernel_launch(void* const* d_in, const int* in_sizes, int n_in,
                              void* d_out, int out_size) {
    const float* x      = (const float*)d_in[0];
    const int*   ei     = (const int*)d_in[1];
    const float* ea     = (const float*)d_in[2];
    const int*   batch  = (const int*)d_in[3];
    const float* in_W   = (const float*)d_in[4];
    const float* in_b   = (const float*)d_in[5];
    const float* edge_W = (const float*)d_in[6];
    const float* edge_b = (const float*)d_in[7];
    const float* mlp_W1 = (const float*)d_in[8];
    const float* mlp_b1 = (const float*)d_in[9];
    const float* bn1_g  = (const float*)d_in[10];
    const float* bn1_b  = (const float*)d_in[11];
    const float* bn1_rm = (const float*)d_in[12];
    const float* bn1_rv = (const float*)d_in[13];
    const float* mlp_W2 = (const float*)d_in[14];
    const float* mlp_b2 = (const float*)d_in[15];
    const float* bn2_g  = (const float*)d_in[16];
    const float* bn2_b  = (const float*)d_in[17];
    const float* bn2_rm = (const float*)d_in[18];
    const float* bn2_rv = (const float*)d_in[19];
    const float* eps    = (const float*)d_in[20];
    const float* ln_g   = (const float*)d_in[21];
    const float* ln_b   = (const float*)d_in[22];
    const float* out_W1 = (const float*)d_in[23];
    const float* out_b1 = (const float*)d_in[24];
    const float* out_W2 = (const float*)d_in[25];
    const float* out_b2 = (const float*)d_in[26];

    int N = in_sizes[0] / 12;
    int E = in_sizes[2] / 3;
    int B = out_size / 128 - N;
    const int* src = ei;
    const int* dst = ei + E;
    float* node_emb  = (float*)d_out;
    float* graph_emb = node_emb + (size_t)N * 128;

    float *p_z, *p_t1, *p_hcat, *p_o1;
    __nv_bfloat16 *p_wh, *p_wl;
    cudaGetSymbolAddress((void**)&p_z,    g_z);
    cudaGetSymbolAddress((void**)&p_t1,   g_t1);
    cudaGetSymbolAddress((void**)&p_hcat, g_hcat);
    cudaGetSymbolAddress((void**)&p_o1,   g_o1);
    cudaGetSymbolAddress((void**)&p_wh,   g_wth);
    cudaGetSymbolAddress((void**)&p_wl,   g_wtl);

    // weight prep: transpose + bf16 hi/lo split (cheap, once per launch)
    for (int l = 0; l < 3; l++) {
        k_prep<<<(128 * 256 + 255) / 256, 256>>>(mlp_W1 + (size_t)l * 32768, 128, 256,
                                                 p_wh + l * 32768, p_wl + l * 32768);
        k_prep<<<(256 * 128 + 255) / 256, 256>>>(mlp_W2 + (size_t)l * 32768, 256, 128,
                                                 p_wh + 98304 + l * 32768, p_wl + 98304 + l * 32768);
    }
    k_prep<<<(512 * 128 + 255) / 256, 256>>>(out_W1, 512, 128, p_wh + 196608, p_wl + 196608);
    k_prep<<<(128 * 128 + 255) / 256, 256>>>(out_W2, 128, 128, p_wh + 262144, p_wl + 262144);

    // input projection + CSR build
    k_in_proj<<<N, 128>>>(x, in_W, in_b);
    k_zero_deg<<<(N + 255) / 256, 256>>>(N);
    k_count<<<(E + 255) / 256, 256>>>(dst, E);
    int nb = (N + 511) / 512;
    k_scan1<<<nb, 512>>>(N);
    k_scan2<<<1, 256>>>(nb);
    k_scan3<<<(N + 255) / 256, 256>>>(N, E);
    k_scatter<<<(E + 255) / 256, 256>>>(src, dst, ea, E);

    int gridM = (N + 127) / 128;
    for (int l = 0; l < 3; l++) {
        k_aggregate<<<(N * 32 + 255) / 256, 256>>>(edge_W + l * 384, edge_b + l * 128, eps, l, N);
        dim3 g1(2, gridM);
        k_mma<2><<<g1, 256>>>(p_z, 128, p_wh + l * 32768, p_wl + l * 32768, 128,
                              p_t1, 256, N,
                              mlp_b1 + l * 256, bn1_g + l * 256, bn1_b + l * 256,
                              bn1_rm + l * 256, bn1_rv + l * 256,
                              nullptr, 0, nullptr, nullptr);
        dim3 g2(1, gridM);
        k_mma<3><<<g2, 256>>>(p_t1, 256, p_wh + 98304 + l * 32768, p_wl + 98304 + l * 32768, 256,
                              p_hcat + (l + 1) * 128, 512, N,
                              mlp_b2 + l * 128, bn2_g + l * 128, bn2_b + l * 128,
                              bn2_rm + l * 128, bn2_rv + l * 128,
                              p_hcat + l * 128, 512, ln_g + l * 128, ln_b + l * 128);
    }

    dim3 go(1, gridM);
    k_mma<1><<<go, 256>>>(p_hcat, 512, p_wh + 196608, p_wl + 196608, 512,
                          p_o1, 128, N,
                          out_b1, nullptr, nullptr, nullptr, nullptr,
                          nullptr, 0, nullptr, nullptr);
    k_mma<0><<<go, 256>>>(p_o1, 128, p_wh + 262144, p_wl + 262144, 128,
                          node_emb, 128, N,
                          out_b2, nullptr, nullptr, nullptr, nullptr,
                          nullptr, 0, nullptr, nullptr);

    k_zero_pool<<<(B * 128 + 255) / 256, 256>>>(B);
    k_pool_acc<<<(N + 63) / 64, 128>>>(node_emb, batch, N);
    k_pool_fin<<<(B * 128 + 255) / 256, 256>>>(graph_emb, B);
}

// round 7
// speedup vs baseline: 2.1783x; 1.1784x over previous
#include <cuda_runtime.h>
#include <cuda_fp16.h>
#include <cstdint>
#include <math.h>

#define MAXN 100000
#define MAXE 600000

// ---------------- scratch (no allocations allowed) ----------------
__device__ __align__(16) float  g_hcat[(size_t)MAXN * 512];   // h0|h1|h2|h3 per node
__device__ __align__(16) float  g_z   [(size_t)MAXN * 128];
__device__ __align__(16) float  g_t1  [(size_t)MAXN * 256];
__device__ __align__(16) float  g_o1  [(size_t)MAXN * 128];
__device__ int    g_deg   [MAXN];
__device__ int    g_rowptr[MAXN + 1];
__device__ int    g_cursor[MAXN];
__device__ int    g_bsum  [256];
__device__ int    g_boff  [256];
__device__ int    g_srcs  [MAXE];
__device__ float4 g_eas   [MAXE];
__device__ float  g_gsum  [64 * 128];
__device__ float  g_cnt   [64];
// split fp16 weights, transposed to [N][K]
__device__ __align__(16) __half g_wth[278528];
__device__ __align__(16) __half g_wtl[278528];

// ---------------- input projection ----------------
__global__ void k_in_proj(const float* __restrict__ x, const float* __restrict__ W,
                          const float* __restrict__ b) {
    int node = blockIdx.x;
    int c = threadIdx.x;
    __shared__ float xs[12];
    if (c < 12) xs[c] = x[node * 12 + c];
    __syncthreads();
    float a = b[c];
#pragma unroll
    for (int k = 0; k < 12; k++) a += xs[k] * W[k * 128 + c];
    g_hcat[(size_t)node * 512 + c] = a;
}

// ---------------- CSR build ----------------
__global__ void k_zero_deg(int n) {
    int i = blockIdx.x * blockDim.x + threadIdx.x;
    if (i < n) g_deg[i] = 0;
}
__global__ void k_count(const int* __restrict__ dst, int e) {
    int i = blockIdx.x * blockDim.x + threadIdx.x;
    if (i < e) atomicAdd(&g_deg[dst[i]], 1);
}
__global__ void k_scan1(int n) {
    int t = threadIdx.x, b = blockIdx.x;
    int i = b * 512 + t;
    int v = (i < n) ? g_deg[i] : 0;
    int lane = t & 31, w = t >> 5;
    int x = v;
#pragma unroll
    for (int o = 1; o < 32; o <<= 1) {
        int y = __shfl_up_sync(0xFFFFFFFFu, x, o);
        if (lane >= o) x += y;
    }
    __shared__ int ws[16];
    if (lane == 31) ws[w] = x;
    __syncthreads();
    if (w == 0) {
        int y = (lane < 16) ? ws[lane] : 0;
#pragma unroll
        for (int o = 1; o < 16; o <<= 1) {
            int z = __shfl_up_sync(0xFFFFFFFFu, y, o);
            if (lane >= o) y += z;
        }
        if (lane < 16) ws[lane] = y;
    }
    __syncthreads();
    int incl = x + (w > 0 ? ws[w - 1] : 0);
    if (i < n) g_rowptr[i] = incl - v;
    if (t == 511) g_bsum[b] = incl;
}
__global__ void k_scan2(int nb) {
    __shared__ int s[256];
    int t = threadIdx.x;
    s[t] = (t < nb) ? g_bsum[t] : 0;
    __syncthreads();
    for (int o = 1; o < 256; o <<= 1) {
        int v = (t >= o) ? s[t - o] : 0;
        __syncthreads();
        s[t] += v;
        __syncthreads();
    }
    g_boff[t] = (t == 0) ? 0 : s[t - 1];
}
__global__ void k_scan3(int n, int e) {
    int i = blockIdx.x * blockDim.x + threadIdx.x;
    if (i < n) {
        int r = g_rowptr[i] + g_boff[i >> 9];
        g_rowptr[i] = r;
        g_cursor[i] = r;
    }
    if (i == 0) g_rowptr[n] = e;
}
__global__ void k_scatter(const int* __restrict__ src, const int* __restrict__ dst,
                          const float* __restrict__ ea, int e) {
    int i = blockIdx.x * blockDim.x + threadIdx.x;
    if (i >= e) return;
    int d = dst[i];
    int p = atomicAdd(&g_cursor[d], 1);
    g_srcs[p] = src[i];
    float4 v; v.x = ea[3 * i]; v.y = ea[3 * i + 1]; v.z = ea[3 * i + 2]; v.w = 0.f;
    g_eas[p] = v;
}

// ---------------- aggregation ----------------
__global__ void k_aggregate(const float* __restrict__ edgeW, const float* __restrict__ edgeb,
                            const float* __restrict__ eps, int l, int n) {
    int gid = blockIdx.x * blockDim.x + threadIdx.x;
    int node = gid >> 5, lane = gid & 31;
    if (node >= n) return;
    int c = lane * 4;
    float4 w0 = *(const float4*)(edgeW + c);
    float4 w1 = *(const float4*)(edgeW + 128 + c);
    float4 w2 = *(const float4*)(edgeW + 256 + c);
    float4 eb = *(const float4*)(edgeb + c);
    float ep = 1.f + eps[l];
    const float* hb = g_hcat + (size_t)l * 128;
    float4 hh = *(const float4*)(hb + (size_t)node * 512 + c);
    float4 acc = make_float4(ep * hh.x, ep * hh.y, ep * hh.z, ep * hh.w);
    int j0 = g_rowptr[node], j1 = g_rowptr[node + 1];
    for (int j = j0; j < j1; j++) {
        int s = g_srcs[j];
        float4 hs = *(const float4*)(hb + (size_t)s * 512 + c);
        float4 a = g_eas[j];
        acc.x += hs.x + w0.x * a.x + w1.x * a.y + w2.x * a.z + eb.x;
        acc.y += hs.y + w0.y * a.x + w1.y * a.y + w2.y * a.z + eb.y;
        acc.z += hs.z + w0.z * a.x + w1.z * a.y + w2.z * a.z + eb.z;
        acc.w += hs.w + w0.w * a.x + w1.w * a.y + w2.w * a.z + eb.w;
    }
    *(float4*)(g_z + (size_t)node * 128 + c) = acc;
}

// ---------------- weight prep: transpose + fp16 hi/lo split ----------------
__global__ void k_prep(const float* __restrict__ W, int K, int N,
                       __half* __restrict__ oh, __half* __restrict__ ol) {
    int i = blockIdx.x * blockDim.x + threadIdx.x;
    if (i >= K * N) return;
    int k = i / N, n = i % N;
    float x = W[i];
    __half h = __float2half_rn(x);
    __half l = __float2half_rn(x - __half2float(h));
    oh[n * K + k] = h;
    ol[n * K + k] = l;
}

// ---------------- tensor-core GEMM (fp16, split-B x2 MMA), fused epilogue ----------------
__device__ __forceinline__ void mma16816(float* c, const unsigned* a, const unsigned* b) {
    asm volatile(
        "mma.sync.aligned.m16n8k16.row.col.f32.f16.f16.f32 "
        "{%0,%1,%2,%3}, {%4,%5,%6,%7}, {%8,%9}, {%0,%1,%2,%3};\n"
        : "+f"(c[0]), "+f"(c[1]), "+f"(c[2]), "+f"(c[3])
        : "r"(a[0]), "r"(a[1]), "r"(a[2]), "r"(a[3]), "r"(b[0]), "r"(b[1]));
}
__device__ __forceinline__ void ldm_x4(unsigned* r, uint32_t a) {
    asm volatile("ldmatrix.sync.aligned.m8n8.x4.shared.b16 {%0,%1,%2,%3}, [%4];"
        : "=r"(r[0]), "=r"(r[1]), "=r"(r[2]), "=r"(r[3]) : "r"(a));
}
__device__ __forceinline__ uint32_t smem_u32(const void* p) {
    uint32_t a;
    asm("{ .reg .u64 t; cvta.to.shared.u64 t, %1; cvt.u32.u64 %0, t; }" : "=r"(a) : "l"(p));
    return a;
}
__device__ __forceinline__ uint32_t pkh2(float a, float b) {
    __half2 h = __floats2half2_rn(a, b);
    return *(uint32_t*)&h;
}

// smem row stride in ushorts: 40 -> 80 B/row (16B-aligned rows, conflict-free ldmatrix)
#define SMS 40

template<int EPI>
__global__ __launch_bounds__(256) void k_mma(
    const float* __restrict__ A, int lda,
    const __half* __restrict__ Wh, const __half* __restrict__ Wl, int K,
    float* __restrict__ C, int ldc, int M,
    const float* __restrict__ bias,
    const float* __restrict__ bng, const float* __restrict__ bnb,
    const float* __restrict__ bnrm, const float* __restrict__ bnrv,
    const float* __restrict__ Res, int ldr,
    const float* __restrict__ lng, const float* __restrict__ lnb) {
    __shared__ __align__(16) unsigned short sA[128 * SMS];
    __shared__ __align__(16) unsigned short sBh[128 * SMS], sBl[128 * SMS];
    __shared__ float sRed[2][128][2];

    int tid = threadIdx.x, lane = tid & 31, wid = tid >> 5;
    int wy = wid & 3, wx = wid >> 2;          // 4x2 warp grid
    int mW = wy * 32, nW = wx * 64;
    int g = lane >> 2, qt = lane & 3;
    int rowBase = blockIdx.y * 128, colBase = blockIdx.x * 128;

    float c[2][8][4];
#pragma unroll
    for (int i = 0; i < 2; i++)
#pragma unroll
        for (int j = 0; j < 8; j++)
#pragma unroll
            for (int m = 0; m < 4; m++) c[i][j][m] = 0.f;

    // ldmatrix base addresses (bytes)
    uint32_t aOff = (uint32_t)((mW + (lane & 15)) * SMS + ((lane >> 4) << 3)) * 2;
    uint32_t bOff = (uint32_t)((nW + ((lane >> 4) << 3) + (lane & 7)) * SMS + (((lane >> 3) & 1) << 3)) * 2;
    uint32_t sAB  = smem_u32(sA) + aOff;
    uint32_t sBhB = smem_u32(sBh) + bOff, sBlB = smem_u32(sBl) + bOff;

    // tile-load index precompute
    int a_row[4], a_k[4];
#pragma unroll
    for (int i = 0; i < 4; i++) { int v = tid + i * 256; a_row[i] = v >> 3; a_k[i] = (v & 7) * 4; }
    int b_n[2], b_k[2];
#pragma unroll
    for (int i = 0; i < 2; i++) { int v = tid + i * 256; b_n[i] = v >> 2; b_k[i] = (v & 3) * 8; }

    float4 aP[4];
    uint4 bPh[2], bPl[2];

    // prologue: load tile 0
#pragma unroll
    for (int i = 0; i < 4; i++) {
        int gr = rowBase + a_row[i];
        aP[i] = (gr < M) ? *(const float4*)(A + (size_t)gr * lda + a_k[i])
                         : make_float4(0.f, 0.f, 0.f, 0.f);
    }
#pragma unroll
    for (int i = 0; i < 2; i++) {
        size_t off = (size_t)(colBase + b_n[i]) * K + b_k[i];
        bPh[i] = *(const uint4*)(Wh + off);
        bPl[i] = *(const uint4*)(Wl + off);
    }

    int nk = K >> 5;
    for (int t = 0; t < nk; t++) {
        // store staged tile to smem (A: fp32 -> fp16)
#pragma unroll
        for (int i = 0; i < 4; i++) {
            uint2 ua;
            ua.x = pkh2(aP[i].x, aP[i].y);
            ua.y = pkh2(aP[i].z, aP[i].w);
            *(uint2*)&sA[a_row[i] * SMS + a_k[i]] = ua;
        }
#pragma unroll
        for (int i = 0; i < 2; i++) {
            *(uint4*)&sBh[b_n[i] * SMS + b_k[i]] = bPh[i];
            *(uint4*)&sBl[b_n[i] * SMS + b_k[i]] = bPl[i];
        }
        __syncthreads();

        // prefetch next tile into registers
        if (t + 1 < nk) {
            int k0 = (t + 1) << 5;
#pragma unroll
            for (int i = 0; i < 4; i++) {
                int gr = rowBase + a_row[i];
                aP[i] = (gr < M) ? *(const float4*)(A + (size_t)gr * lda + k0 + a_k[i])
                                 : make_float4(0.f, 0.f, 0.f, 0.f);
            }
#pragma unroll
            for (int i = 0; i < 2; i++) {
                size_t off = (size_t)(colBase + b_n[i]) * K + k0 + b_k[i];
                bPh[i] = *(const uint4*)(Wh + off);
                bPl[i] = *(const uint4*)(Wl + off);
            }
        }

        // compute: 2 k16 chunks, fragments via ldmatrix.x4
#pragma unroll
        for (int kc = 0; kc < 2; kc++) {
            uint32_t kByte = (uint32_t)(kc * 16) * 2;
            unsigned ah[2][4], bh[8][2], bl[8][2];
#pragma unroll
            for (int i = 0; i < 2; i++) {
                uint32_t rb = (uint32_t)(i * 16 * SMS) * 2 + kByte;
                ldm_x4(ah[i], sAB + rb);
            }
#pragma unroll
            for (int j2 = 0; j2 < 4; j2++) {
                uint32_t rb = (uint32_t)(j2 * 16 * SMS) * 2 + kByte;
                ldm_x4(&bh[j2 * 2][0], sBhB + rb);
                ldm_x4(&bl[j2 * 2][0], sBlB + rb);
            }
#pragma unroll
            for (int i = 0; i < 2; i++)
#pragma unroll
                for (int j = 0; j < 8; j++) {
                    mma16816(c[i][j], ah[i], bh[j]);
                    mma16816(c[i][j], ah[i], bl[j]);
                }
        }
        if (t + 1 < nk) __syncthreads();
    }

    // epilogue: per-column scale/shift
    float cs[8][2], ct[8][2];
#pragma unroll
    for (int j = 0; j < 8; j++) {
#pragma unroll
        for (int h = 0; h < 2; h++) {
            int col = colBase + nW + j * 8 + qt * 2 + h;
            if (EPI >= 2) {
                float s = bng[col] * rsqrtf(bnrv[col] + 1e-5f);
                cs[j][h] = s; ct[j][h] = bnb[col] + (bias[col] - bnrm[col]) * s;
            } else { cs[j][h] = 1.f; ct[j][h] = bias[col]; }
        }
    }

    if (EPI == 3) {
        float s[2][2], q[2][2];
#pragma unroll
        for (int i = 0; i < 2; i++) { s[i][0] = s[i][1] = 0.f; q[i][0] = q[i][1] = 0.f; }
#pragma unroll
        for (int i = 0; i < 2; i++) {
            int r1 = rowBase + mW + i * 16 + g, r2 = r1 + 8;
#pragma unroll
            for (int j = 0; j < 8; j++) {
                int colL = nW + j * 8 + qt * 2;
                float2 res1 = make_float2(0.f, 0.f), res2 = make_float2(0.f, 0.f);
                if (r1 < M) res1 = *(const float2*)(Res + (size_t)r1 * ldr + colL);
                if (r2 < M) res2 = *(const float2*)(Res + (size_t)r2 * ldr + colL);
                float v0 = fmaxf(c[i][j][0] * cs[j][0] + ct[j][0], 0.f) + res1.x;
                float v1 = fmaxf(c[i][j][1] * cs[j][1] + ct[j][1], 0.f) + res1.y;
                float v2 = fmaxf(c[i][j][2] * cs[j][0] + ct[j][0], 0.f) + res2.x;
                float v3 = fmaxf(c[i][j][3] * cs[j][1] + ct[j][1], 0.f) + res2.y;
                c[i][j][0] = v0; c[i][j][1] = v1; c[i][j][2] = v2; c[i][j][3] = v3;
                s[i][0] += v0 + v1; q[i][0] += v0 * v0 + v1 * v1;
                s[i][1] += v2 + v3; q[i][1] += v2 * v2 + v3 * v3;
            }
        }
#pragma unroll
        for (int i = 0; i < 2; i++)
#pragma unroll
            for (int h = 0; h < 2; h++) {
                s[i][h] += __shfl_xor_sync(0xFFFFFFFFu, s[i][h], 1);
                s[i][h] += __shfl_xor_sync(0xFFFFFFFFu, s[i][h], 2);
                q[i][h] += __shfl_xor_sync(0xFFFFFFFFu, q[i][h], 1);
                q[i][h] += __shfl_xor_sync(0xFFFFFFFFu, q[i][h], 2);
            }
        if (qt == 0) {
#pragma unroll
            for (int i = 0; i < 2; i++)
#pragma unroll
                for (int h = 0; h < 2; h++) {
                    int lr = mW + i * 16 + g + h * 8;
                    sRed[0][lr][wx] = s[i][h];
                    sRed[1][lr][wx] = q[i][h];
                }
        }
        __syncthreads();
#pragma unroll
        for (int i = 0; i < 2; i++)
#pragma unroll
            for (int h = 0; h < 2; h++) {
                int lr = mW + i * 16 + g + h * 8;
                int gr = rowBase + lr;
                float ts = sRed[0][lr][0] + sRed[0][lr][1];
                float tq = sRed[1][lr][0] + sRed[1][lr][1];
                float mu = ts * (1.f / 128.f);
                float var = tq * (1.f / 128.f) - mu * mu;
                float rr = rsqrtf(var + 1e-5f);
                if (gr < M) {
#pragma unroll
                    for (int j = 0; j < 8; j++) {
                        int colL = nW + j * 8 + qt * 2;
                        float2 o;
                        o.x = (c[i][j][h * 2]     - mu) * rr * lng[colL]     + lnb[colL];
                        o.y = (c[i][j][h * 2 + 1] - mu) * rr * lng[colL + 1] + lnb[colL + 1];
                        *(float2*)(C + (size_t)gr * ldc + colL) = o;
                    }
                }
            }
    } else {
#pragma unroll
        for (int i = 0; i < 2; i++) {
            int r1 = rowBase + mW + i * 16 + g, r2 = r1 + 8;
#pragma unroll
            for (int j = 0; j < 8; j++) {
                int col = colBase + nW + j * 8 + qt * 2;
                float o0 = c[i][j][0] * cs[j][0] + ct[j][0];
                float o1 = c[i][j][1] * cs[j][1] + ct[j][1];
                float o2 = c[i][j][2] * cs[j][0] + ct[j][0];
                float o3 = c[i][j][3] * cs[j][1] + ct[j][1];
                if (EPI >= 1) {
                    o0 = fmaxf(o0, 0.f); o1 = fmaxf(o1, 0.f);
                    o2 = fmaxf(o2, 0.f); o3 = fmaxf(o3, 0.f);
                }
                if (r1 < M) { float2 o; o.x = o0; o.y = o1; *(float2*)(C + (size_t)r1 * ldc + col) = o; }
                if (r2 < M) { float2 o; o.x = o2; o.y = o3; *(float2*)(C + (size_t)r2 * ldc + col) = o; }
            }
        }
    }
}

// ---------------- global mean pool ----------------
__global__ void k_zero_pool(int b) {
    int i = blockIdx.x * blockDim.x + threadIdx.x;
    if (i < b * 128) g_gsum[i] = 0.f;
    if (i < b) g_cnt[i] = 0.f;
}
__global__ void k_pool_acc(const float* __restrict__ emb, const int* __restrict__ batch, int n) {
    int c = threadIdx.x;
    int base = blockIdx.x * 64;
    float acc = 0.f, cnt = 0.f;
    int cur = -1;
    for (int i = 0; i < 64; i++) {
        int nd = base + i;
        if (nd >= n) break;
        int g = batch[nd];
        if (g != cur) {
            if (cur >= 0) {
                atomicAdd(&g_gsum[cur * 128 + c], acc);
                if (c == 0) atomicAdd(&g_cnt[cur], cnt);
            }
            cur = g; acc = 0.f; cnt = 0.f;
        }
        acc += emb[(size_t)nd * 128 + c];
        cnt += 1.f;
    }
    if (cur >= 0) {
        atomicAdd(&g_gsum[cur * 128 + c], acc);
        if (c == 0) atomicAdd(&g_cnt[cur], cnt);
    }
}
__global__ void k_pool_fin(float* __restrict__ out, int b) {
    int i = blockIdx.x * blockDim.x + threadIdx.x;
    if (i >= b * 128) return;
    out[i] = g_gsum[i] / fmaxf(g_cnt[i >> 7], 1.f);
}

// ---------------- launch ----------------
extern "C" void kernel_launch(void* const* d_in, const int* in_sizes, int n_in,
                              void* d_out, int out_size) {
    const float* x      = (const float*)d_in[0];
    const int*   ei     = (const int*)d_in[1];
    const float* ea     = (const float*)d_in[2];
    const int*   batch  = (const int*)d_in[3];
    const float* in_W   = (const float*)d_in[4];
    const float* in_b   = (const float*)d_in[5];
    const float* edge_W = (const float*)d_in[6];
    const float* edge_b = (const float*)d_in[7];
    const float* mlp_W1 = (const float*)d_in[8];
    const float* mlp_b1 = (const float*)d_in[9];
    const float* bn1_g  = (const float*)d_in[10];
    const float* bn1_b  = (const float*)d_in[11];
    const float* bn1_rm = (const float*)d_in[12];
    const float* bn1_rv = (const float*)d_in[13];
    const float* mlp_W2 = (const float*)d_in[14];
    const float* mlp_b2 = (const float*)d_in[15];
    const float* bn2_g  = (const float*)d_in[16];
    const float* bn2_b  = (const float*)d_in[17];
    const float* bn2_rm = (const float*)d_in[18];
    const float* bn2_rv = (const float*)d_in[19];
    const float* eps    = (const float*)d_in[20];
    const float* ln_g   = (const float*)d_in[21];
    const float* ln_b   = (const float*)d_in[22];
    const float* out_W1 = (const float*)d_in[23];
    const float* out_b1 = (const float*)d_in[24];
    const float* out_W2 = (const float*)d_in[25];
    const float* out_b2 = (const float*)d_in[26];

    int N = in_sizes[0] / 12;
    int E = in_sizes[2] / 3;
    int B = out_size / 128 - N;
    const int* src = ei;
    const int* dst = ei + E;
    float* node_emb  = (float*)d_out;
    float* graph_emb = node_emb + (size_t)N * 128;

    float *p_z, *p_t1, *p_hcat, *p_o1;
    __half *p_wh, *p_wl;
    cudaGetSymbolAddress((void**)&p_z,    g_z);
    cudaGetSymbolAddress((void**)&p_t1,   g_t1);
    cudaGetSymbolAddress((void**)&p_hcat, g_hcat);
    cudaGetSymbolAddress((void**)&p_o1,   g_o1);
    cudaGetSymbolAddress((void**)&p_wh,   g_wth);
    cudaGetSymbolAddress((void**)&p_wl,   g_wtl);

    // weight prep: transpose + fp16 hi/lo split (cheap, once per launch)
    for (int l = 0; l < 3; l++) {
        k_prep<<<(128 * 256 + 255) / 256, 256>>>(mlp_W1 + (size_t)l * 32768, 128, 256,
                                                 p_wh + l * 32768, p_wl + l * 32768);
        k_prep<<<(256 * 128 + 255) / 256, 256>>>(mlp_W2 + (size_t)l * 32768, 256, 128,
                                                 p_wh + 98304 + l * 32768, p_wl + 98304 + l * 32768);
    }
    k_prep<<<(512 * 128 + 255) / 256, 256>>>(out_W1, 512, 128, p_wh + 196608, p_wl + 196608);
    k_prep<<<(128 * 128 + 255) / 256, 256>>>(out_W2, 128, 128, p_wh + 262144, p_wl + 262144);

    // input projection + CSR build
    k_in_proj<<<N, 128>>>(x, in_W, in_b);
    k_zero_deg<<<(N + 255) / 256, 256>>>(N);
    k_count<<<(E + 255) / 256, 256>>>(dst, E);
    int nb = (N + 511) / 512;
    k_scan1<<<nb, 512>>>(N);
    k_scan2<<<1, 256>>>(nb);
    k_scan3<<<(N + 255) / 256, 256>>>(N, E);
    k_scatter<<<(E + 255) / 256, 256>>>(src, dst, ea, E);

    int gridM = (N + 127) / 128;
    for (int l = 0; l < 3; l++) {
        k_aggregate<<<(N * 32 + 255) / 256, 256>>>(edge_W + l * 384, edge_b + l * 128, eps, l, N);
        dim3 g1(2, gridM);
        k_mma<2><<<g1, 256>>>(p_z, 128, p_wh + l * 32768, p_wl + l * 32768, 128,
                              p_t1, 256, N,
                              mlp_b1 + l * 256, bn1_g + l * 256, bn1_b + l * 256,
                              bn1_rm + l * 256, bn1_rv + l * 256,
                              nullptr, 0, nullptr, nullptr);
        dim3 g2(1, gridM);
        k_mma<3><<<g2, 256>>>(p_t1, 256, p_wh + 98304 + l * 32768, p_wl + 98304 + l * 32768, 256,
                              p_hcat + (l + 1) * 128, 512, N,
                              mlp_b2 + l * 128, bn2_g + l * 128, bn2_b + l * 128,
                              bn2_rm + l * 128, bn2_rv + l * 128,
                              p_hcat + l * 128, 512, ln_g + l * 128, ln_b + l * 128);
    }

    dim3 go(1, gridM);
    k_mma<1><<<go, 256>>>(p_hcat, 512, p_wh + 196608, p_wl + 196608, 512,
                          p_o1, 128, N,
                          out_b1, nullptr, nullptr, nullptr, nullptr,
                          nullptr, 0, nullptr, nullptr);
    k_mma<0><<<go, 256>>>(p_o1, 128, p_wh + 262144, p_wl + 262144, 128,
                          node_emb, 128, N,
                          out_b2, nullptr, nullptr, nullptr, nullptr,
                          nullptr, 0, nullptr, nullptr);

    k_zero_pool<<<(B * 128 + 255) / 256, 256>>>(B);
    k_pool_acc<<<(N + 63) / 64, 128>>>(node_emb, batch, N);
    k_pool_fin<<<(B * 128 + 255) / 256, 256>>>(graph_emb, B);
}

// round 8
// speedup vs baseline: 2.5924x; 1.1901x over previous
#include <cuda_runtime.h>
#include <cuda_fp16.h>
#include <cstdint>
#include <math.h>

#define MAXN 100000
#define MAXE 600000

// ---------------- scratch (no allocations allowed) ----------------
__device__ __align__(16) float  g_hcat[(size_t)MAXN * 512];   // h0|h1|h2|h3 per node
__device__ __align__(16) float  g_z   [(size_t)MAXN * 128];
__device__ __align__(16) float  g_t1  [(size_t)MAXN * 256];
__device__ __align__(16) float  g_o1  [(size_t)MAXN * 128];
__device__ int    g_deg   [MAXN];
__device__ int    g_rowptr[MAXN + 1];
__device__ int    g_cursor[MAXN];
__device__ int    g_bsum  [256];
__device__ int    g_boff  [256];
__device__ int    g_srcs  [MAXE];
__device__ float4 g_eas   [MAXE];
__device__ float  g_gsum  [64 * 128];
__device__ float  g_cnt   [64];
// split fp16 weights, transposed to [N][K]
__device__ __align__(16) __half g_wth[278528];
__device__ __align__(16) __half g_wtl[278528];

// ---------------- input projection ----------------
__global__ void k_in_proj(const float* __restrict__ x, const float* __restrict__ W,
                          const float* __restrict__ b) {
    int node = blockIdx.x;
    int c = threadIdx.x;
    __shared__ float xs[12];
    if (c < 12) xs[c] = x[node * 12 + c];
    __syncthreads();
    float a = b[c];
#pragma unroll
    for (int k = 0; k < 12; k++) a += xs[k] * W[k * 128 + c];
    g_hcat[(size_t)node * 512 + c] = a;
}

// ---------------- CSR build ----------------
__global__ void k_zero_deg(int n, int b) {
    int i = blockIdx.x * blockDim.x + threadIdx.x;
    if (i < n) g_deg[i] = 0;
    if (i < b * 128) g_gsum[i] = 0.f;
    if (i < b) g_cnt[i] = 0.f;
}
__global__ void k_count(const int* __restrict__ dst, int e) {
    int i = blockIdx.x * blockDim.x + threadIdx.x;
    if (i < e) atomicAdd(&g_deg[dst[i]], 1);
}
__global__ void k_scan1(int n) {
    int t = threadIdx.x, b = blockIdx.x;
    int i = b * 512 + t;
    int v = (i < n) ? g_deg[i] : 0;
    int lane = t & 31, w = t >> 5;
    int x = v;
#pragma unroll
    for (int o = 1; o < 32; o <<= 1) {
        int y = __shfl_up_sync(0xFFFFFFFFu, x, o);
        if (lane >= o) x += y;
    }
    __shared__ int ws[16];
    if (lane == 31) ws[w] = x;
    __syncthreads();
    if (w == 0) {
        int y = (lane < 16) ? ws[lane] : 0;
#pragma unroll
        for (int o = 1; o < 16; o <<= 1) {
            int z = __shfl_up_sync(0xFFFFFFFFu, y, o);
            if (lane >= o) y += z;
        }
        if (lane < 16) ws[lane] = y;
    }
    __syncthreads();
    int incl = x + (w > 0 ? ws[w - 1] : 0);
    if (i < n) g_rowptr[i] = incl - v;
    if (t == 511) g_bsum[b] = incl;
}
__global__ void k_scan2(int nb) {
    __shared__ int s[256];
    int t = threadIdx.x;
    s[t] = (t < nb) ? g_bsum[t] : 0;
    __syncthreads();
    for (int o = 1; o < 256; o <<= 1) {
        int v = (t >= o) ? s[t - o] : 0;
        __syncthreads();
        s[t] += v;
        __syncthreads();
    }
    g_boff[t] = (t == 0) ? 0 : s[t - 1];
}
__global__ void k_scan3(int n, int e) {
    int i = blockIdx.x * blockDim.x + threadIdx.x;
    if (i < n) {
        int r = g_rowptr[i] + g_boff[i >> 9];
        g_rowptr[i] = r;
        g_cursor[i] = r;
    }
    if (i == 0) g_rowptr[n] = e;
}
__global__ void k_scatter(const int* __restrict__ src, const int* __restrict__ dst,
                          const float* __restrict__ ea, int e) {
    int i = blockIdx.x * blockDim.x + threadIdx.x;
    if (i >= e) return;
    int d = dst[i];
    int p = atomicAdd(&g_cursor[d], 1);
    g_srcs[p] = src[i];
    float4 v; v.x = ea[3 * i]; v.y = ea[3 * i + 1]; v.z = ea[3 * i + 2]; v.w = 0.f;
    g_eas[p] = v;
}

// ---------------- aggregation ----------------
__global__ void k_aggregate(const float* __restrict__ edgeW, const float* __restrict__ edgeb,
                            const float* __restrict__ eps, int l, int n) {
    int gid = blockIdx.x * blockDim.x + threadIdx.x;
    int node = gid >> 5, lane = gid & 31;
    if (node >= n) return;
    int c = lane * 4;
    float4 w0 = *(const float4*)(edgeW + c);
    float4 w1 = *(const float4*)(edgeW + 128 + c);
    float4 w2 = *(const float4*)(edgeW + 256 + c);
    float4 eb = *(const float4*)(edgeb + c);
    float ep = 1.f + eps[l];
    const float* hb = g_hcat + (size_t)l * 128;
    float4 hh = *(const float4*)(hb + (size_t)node * 512 + c);
    float4 acc = make_float4(ep * hh.x, ep * hh.y, ep * hh.z, ep * hh.w);
    int j0 = g_rowptr[node], j1 = g_rowptr[node + 1];
    for (int j = j0; j < j1; j++) {
        int s = g_srcs[j];
        float4 hs = *(const float4*)(hb + (size_t)s * 512 + c);
        float4 a = g_eas[j];
        acc.x += hs.x + w0.x * a.x + w1.x * a.y + w2.x * a.z + eb.x;
        acc.y += hs.y + w0.y * a.x + w1.y * a.y + w2.y * a.z + eb.y;
        acc.z += hs.z + w0.z * a.x + w1.z * a.y + w2.z * a.z + eb.z;
        acc.w += hs.w + w0.w * a.x + w1.w * a.y + w2.w * a.z + eb.w;
    }
    *(float4*)(g_z + (size_t)node * 128 + c) = acc;
}

// ---------------- weight prep: all weights in one kernel ----------------
__global__ void k_prep_all(const float* __restrict__ W1, const float* __restrict__ W2,
                           const float* __restrict__ O1, const float* __restrict__ O2,
                           __half* __restrict__ oh, __half* __restrict__ ol) {
    int i = blockIdx.x * blockDim.x + threadIdx.x;
    if (i >= 278528) return;
    const float* src; int K, N, base, rel;
    if (i < 98304)       { int l = i / 32768; rel = i % 32768; src = W1 + (size_t)l * 32768; K = 128; N = 256; base = l * 32768; }
    else if (i < 196608) { int j = i - 98304; int l = j / 32768; rel = j % 32768; src = W2 + (size_t)l * 32768; K = 256; N = 128; base = 98304 + l * 32768; }
    else if (i < 262144) { rel = i - 196608; src = O1; K = 512; N = 128; base = 196608; }
    else                 { rel = i - 262144; src = O2; K = 128; N = 128; base = 262144; }
    int k = rel / N, n = rel % N;
    float x = src[rel];
    __half h = __float2half_rn(x);
    __half l2 = __float2half_rn(x - __half2float(h));
    oh[base + n * K + k] = h;
    ol[base + n * K + k] = l2;
}

// ---------------- tensor-core GEMM (fp16 split-B, cp.async double-buffer) ----------------
__device__ __forceinline__ void mma16816(float* c, const unsigned* a, const unsigned* b) {
    asm volatile(
        "mma.sync.aligned.m16n8k16.row.col.f32.f16.f16.f32 "
        "{%0,%1,%2,%3}, {%4,%5,%6,%7}, {%8,%9}, {%0,%1,%2,%3};\n"
        : "+f"(c[0]), "+f"(c[1]), "+f"(c[2]), "+f"(c[3])
        : "r"(a[0]), "r"(a[1]), "r"(a[2]), "r"(a[3]), "r"(b[0]), "r"(b[1]));
}
__device__ __forceinline__ void ldm_x4(unsigned* r, uint32_t a) {
    asm volatile("ldmatrix.sync.aligned.m8n8.x4.shared.b16 {%0,%1,%2,%3}, [%4];"
        : "=r"(r[0]), "=r"(r[1]), "=r"(r[2]), "=r"(r[3]) : "r"(a));
}
__device__ __forceinline__ uint32_t smem_u32(const void* p) {
    uint32_t a;
    asm("{ .reg .u64 t; cvta.to.shared.u64 t, %1; cvt.u32.u64 %0, t; }" : "=r"(a) : "l"(p));
    return a;
}
__device__ __forceinline__ void cpa16(uint32_t s, const void* g) {
    asm volatile("cp.async.cg.shared.global [%0], [%1], 16;" :: "r"(s), "l"(g));
}
#define CPA_COMMIT() asm volatile("cp.async.commit_group;" ::: "memory")
#define CPA_WAIT0()  asm volatile("cp.async.wait_group 0;" ::: "memory")
__device__ __forceinline__ uint32_t pkh2(float a, float b) {
    __half2 h = __floats2half2_rn(a, b);
    return *(uint32_t*)&h;
}

// smem row stride in ushorts: 40 -> 80 B/row (16B-aligned rows, conflict-free ldmatrix)
#define SMS 40
#define BUFB 10240u                 // one 128-row tile buffer, bytes
// dyn smem: sA[2] | sBh[2] | sBl[2] | sRed
#define OF_A(s)  ((s) * BUFB)
#define OF_BH(s) (2u * BUFB + (s) * BUFB)
#define OF_BL(s) (4u * BUFB + (s) * BUFB)
#define OF_RED   (6u * BUFB)
#define SMEM_MMA (6 * 10240 + 2048)   // 63488

template<int EPI>
__global__ __launch_bounds__(256, 2) void k_mma(
    const float* __restrict__ A, int lda,
    const __half* __restrict__ Wh, const __half* __restrict__ Wl, int K,
    float* __restrict__ C, int ldc, int M,
    const float* __restrict__ bias,
    const float* __restrict__ bng, const float* __restrict__ bnb,
    const float* __restrict__ bnrm, const float* __restrict__ bnrv,
    const float* __restrict__ Res, int ldr,
    const float* __restrict__ lng, const float* __restrict__ lnb) {
    extern __shared__ __align__(16) char smx[];
    uint32_t smb = smem_u32(smx);
    float* sRedP = (float*)(smx + OF_RED);   // [2][128][2]

    int tid = threadIdx.x, lane = tid & 31, wid = tid >> 5;
    int wy = wid & 3, wx = wid >> 2;          // 4x2 warp grid
    int mW = wy * 32, nW = wx * 64;
    int g = lane >> 2, qt = lane & 3;
    int rowBase = blockIdx.y * 128, colBase = blockIdx.x * 128;

    float c[2][8][4];
#pragma unroll
    for (int i = 0; i < 2; i++)
#pragma unroll
        for (int j = 0; j < 8; j++)
#pragma unroll
            for (int m = 0; m < 4; m++) c[i][j][m] = 0.f;

    // ldmatrix lane offsets (bytes, within a buffer)
    uint32_t aOff = (uint32_t)((mW + (lane & 15)) * SMS + ((lane >> 4) << 3)) * 2;
    uint32_t bOff = (uint32_t)((nW + ((lane >> 4) << 3) + (lane & 7)) * SMS + (((lane >> 3) & 1) << 3)) * 2;

    // tile-load index precompute
    int a_row[4], a_k[4];
#pragma unroll
    for (int i = 0; i < 4; i++) { int v = tid + i * 256; a_row[i] = v >> 3; a_k[i] = (v & 7) * 4; }
    int b_n[2], b_k[2];
#pragma unroll
    for (int i = 0; i < 2; i++) { int v = tid + i * 256; b_n[i] = v >> 2; b_k[i] = (v & 3) * 8; }
    uint32_t bSm[2];
#pragma unroll
    for (int i = 0; i < 2; i++) bSm[i] = (uint32_t)(b_n[i] * SMS + b_k[i]) * 2;
    size_t bGm[2];
#pragma unroll
    for (int i = 0; i < 2; i++) bGm[i] = (size_t)(colBase + b_n[i]) * K + b_k[i];

    float4 aP[4];
    // prologue: cp.async B tile0 -> buf0; load A tile0 into regs
#pragma unroll
    for (int i = 0; i < 2; i++) {
        cpa16(smb + OF_BH(0) + bSm[i], Wh + bGm[i]);
        cpa16(smb + OF_BL(0) + bSm[i], Wl + bGm[i]);
    }
    CPA_COMMIT();
#pragma unroll
    for (int i = 0; i < 4; i++) {
        int gr = rowBase + a_row[i];
        aP[i] = (gr < M) ? *(const float4*)(A + (size_t)gr * lda + a_k[i])
                         : make_float4(0.f, 0.f, 0.f, 0.f);
    }

    int nk = K >> 5;
    for (int t = 0; t < nk; t++) {
        int cur = t & 1, nxt = cur ^ 1;
        // store A tile t (regs -> smem cur)
#pragma unroll
        for (int i = 0; i < 4; i++) {
            uint2 ua;
            ua.x = pkh2(aP[i].x, aP[i].y);
            ua.y = pkh2(aP[i].z, aP[i].w);
            *(uint2*)(smx + OF_A(cur) + (uint32_t)(a_row[i] * SMS + a_k[i]) * 2) = ua;
        }
        CPA_WAIT0();          // B tile t landed
        __syncthreads();      // everyone done with compute t-1; cur fully staged
        if (t + 1 < nk) {
            int k0 = (t + 1) << 5;
#pragma unroll
            for (int i = 0; i < 2; i++) {
                cpa16(smb + OF_BH(nxt) + bSm[i], Wh + bGm[i] + k0);
                cpa16(smb + OF_BL(nxt) + bSm[i], Wl + bGm[i] + k0);
            }
            CPA_COMMIT();
#pragma unroll
            for (int i = 0; i < 4; i++) {
                int gr = rowBase + a_row[i];
                aP[i] = (gr < M) ? *(const float4*)(A + (size_t)gr * lda + k0 + a_k[i])
                                 : make_float4(0.f, 0.f, 0.f, 0.f);
            }
        }
        // compute from cur
        uint32_t aB  = smb + OF_A(cur)  + aOff;
        uint32_t bhB = smb + OF_BH(cur) + bOff;
        uint32_t blB = smb + OF_BL(cur) + bOff;
#pragma unroll
        for (int kc = 0; kc < 2; kc++) {
            uint32_t kByte = (uint32_t)(kc * 16) * 2;
            unsigned ah[2][4], bh[8][2], bl[8][2];
#pragma unroll
            for (int i = 0; i < 2; i++)
                ldm_x4(ah[i], aB + (uint32_t)(i * 16 * SMS) * 2 + kByte);
#pragma unroll
            for (int j2 = 0; j2 < 4; j2++) {
                uint32_t rb = (uint32_t)(j2 * 16 * SMS) * 2 + kByte;
                ldm_x4(&bh[j2 * 2][0], bhB + rb);
                ldm_x4(&bl[j2 * 2][0], blB + rb);
            }
#pragma unroll
            for (int i = 0; i < 2; i++)
#pragma unroll
                for (int j = 0; j < 8; j++) {
                    mma16816(c[i][j], ah[i], bh[j]);
                    mma16816(c[i][j], ah[i], bl[j]);
                }
        }
    }
    __syncthreads();   // protect sRed reuse below

    // epilogue: per-column scale/shift
    float cs[8][2], ct[8][2];
#pragma unroll
    for (int j = 0; j < 8; j++) {
#pragma unroll
        for (int h = 0; h < 2; h++) {
            int col = colBase + nW + j * 8 + qt * 2 + h;
            if (EPI >= 2) {
                float s = bng[col] * rsqrtf(bnrv[col] + 1e-5f);
                cs[j][h] = s; ct[j][h] = bnb[col] + (bias[col] - bnrm[col]) * s;
            } else { cs[j][h] = 1.f; ct[j][h] = bias[col]; }
        }
    }

    if (EPI == 3) {
        float s[2][2], q[2][2];
#pragma unroll
        for (int i = 0; i < 2; i++) { s[i][0] = s[i][1] = 0.f; q[i][0] = q[i][1] = 0.f; }
#pragma unroll
        for (int i = 0; i < 2; i++) {
            int r1 = rowBase + mW + i * 16 + g, r2 = r1 + 8;
#pragma unroll
            for (int j = 0; j < 8; j++) {
                int colL = nW + j * 8 + qt * 2;
                float2 res1 = make_float2(0.f, 0.f), res2 = make_float2(0.f, 0.f);
                if (r1 < M) res1 = *(const float2*)(Res + (size_t)r1 * ldr + colL);
                if (r2 < M) res2 = *(const float2*)(Res + (size_t)r2 * ldr + colL);
                float v0 = fmaxf(c[i][j][0] * cs[j][0] + ct[j][0], 0.f) + res1.x;
                float v1 = fmaxf(c[i][j][1] * cs[j][1] + ct[j][1], 0.f) + res1.y;
                float v2 = fmaxf(c[i][j][2] * cs[j][0] + ct[j][0], 0.f) + res2.x;
                float v3 = fmaxf(c[i][j][3] * cs[j][1] + ct[j][1], 0.f) + res2.y;
                c[i][j][0] = v0; c[i][j][1] = v1; c[i][j][2] = v2; c[i][j][3] = v3;
                s[i][0] += v0 + v1; q[i][0] += v0 * v0 + v1 * v1;
                s[i][1] += v2 + v3; q[i][1] += v2 * v2 + v3 * v3;
            }
        }
#pragma unroll
        for (int i = 0; i < 2; i++)
#pragma unroll
            for (int h = 0; h < 2; h++) {
                s[i][h] += __shfl_xor_sync(0xFFFFFFFFu, s[i][h], 1);
                s[i][h] += __shfl_xor_sync(0xFFFFFFFFu, s[i][h], 2);
                q[i][h] += __shfl_xor_sync(0xFFFFFFFFu, q[i][h], 1);
                q[i][h] += __shfl_xor_sync(0xFFFFFFFFu, q[i][h], 2);
            }
        if (qt == 0) {
#pragma unroll
            for (int i = 0; i < 2; i++)
#pragma unroll
                for (int h = 0; h < 2; h++) {
                    int lr = mW + i * 16 + g + h * 8;
                    sRedP[lr * 2 + wx]       = s[i][h];
                    sRedP[256 + lr * 2 + wx] = q[i][h];
                }
        }
        __syncthreads();
#pragma unroll
        for (int i = 0; i < 2; i++)
#pragma unroll
            for (int h = 0; h < 2; h++) {
                int lr = mW + i * 16 + g + h * 8;
                int gr = rowBase + lr;
                float ts = sRedP[lr * 2] + sRedP[lr * 2 + 1];
                float tq = sRedP[256 + lr * 2] + sRedP[256 + lr * 2 + 1];
                float mu = ts * (1.f / 128.f);
                float var = tq * (1.f / 128.f) - mu * mu;
                float rr = rsqrtf(var + 1e-5f);
                if (gr < M) {
#pragma unroll
                    for (int j = 0; j < 8; j++) {
                        int colL = nW + j * 8 + qt * 2;
                        float2 o;
                        o.x = (c[i][j][h * 2]     - mu) * rr * lng[colL]     + lnb[colL];
                        o.y = (c[i][j][h * 2 + 1] - mu) * rr * lng[colL + 1] + lnb[colL + 1];
                        *(float2*)(C + (size_t)gr * ldc + colL) = o;
                    }
                }
            }
    } else {
#pragma unroll
        for (int i = 0; i < 2; i++) {
            int r1 = rowBase + mW + i * 16 + g, r2 = r1 + 8;
#pragma unroll
            for (int j = 0; j < 8; j++) {
                int col = colBase + nW + j * 8 + qt * 2;
                float o0 = c[i][j][0] * cs[j][0] + ct[j][0];
                float o1 = c[i][j][1] * cs[j][1] + ct[j][1];
                float o2 = c[i][j][2] * cs[j][0] + ct[j][0];
                float o3 = c[i][j][3] * cs[j][1] + ct[j][1];
                if (EPI >= 1) {
                    o0 = fmaxf(o0, 0.f); o1 = fmaxf(o1, 0.f);
                    o2 = fmaxf(o2, 0.f); o3 = fmaxf(o3, 0.f);
                }
                if (r1 < M) { float2 o; o.x = o0; o.y = o1; *(float2*)(C + (size_t)r1 * ldc + col) = o; }
                if (r2 < M) { float2 o; o.x = o2; o.y = o3; *(float2*)(C + (size_t)r2 * ldc + col) = o; }
            }
        }
    }
}

// ---------------- global mean pool ----------------
__global__ void k_pool_acc(const float* __restrict__ emb, const int* __restrict__ batch, int n) {
    int c = threadIdx.x;
    int base = blockIdx.x * 64;
    float acc = 0.f, cnt = 0.f;
    int cur = -1;
    for (int i = 0; i < 64; i++) {
        int nd = base + i;
        if (nd >= n) break;
        int g = batch[nd];
        if (g != cur) {
            if (cur >= 0) {
                atomicAdd(&g_gsum[cur * 128 + c], acc);
                if (c == 0) atomicAdd(&g_cnt[cur], cnt);
            }
            cur = g; acc = 0.f; cnt = 0.f;
        }
        acc += emb[(size_t)nd * 128 + c];
        cnt += 1.f;
    }
    if (cur >= 0) {
        atomicAdd(&g_gsum[cur * 128 + c], acc);
        if (c == 0) atomicAdd(&g_cnt[cur], cnt);
    }
}
__global__ void k_pool_fin(float* __restrict__ out, int b) {
    int i = blockIdx.x * blockDim.x + threadIdx.x;
    if (i >= b * 128) return;
    out[i] = g_gsum[i] / fmaxf(g_cnt[i >> 7], 1.f);
}

// ---------------- launch ----------------
extern "C" void kernel_launch(void* const* d_in, const int* in_sizes, int n_in,
                              void* d_out, int out_size) {
    const float* x      = (const float*)d_in[0];
    const int*   ei     = (const int*)d_in[1];
    const float* ea     = (const float*)d_in[2];
    const int*   batch  = (const int*)d_in[3];
    const float* in_W   = (const float*)d_in[4];
    const float* in_b   = (const float*)d_in[5];
    const float* edge_W = (const float*)d_in[6];
    const float* edge_b = (const float*)d_in[7];
    const float* mlp_W1 = (const float*)d_in[8];
    const float* mlp_b1 = (const float*)d_in[9];
    const float* bn1_g  = (const float*)d_in[10];
    const float* bn1_b  = (const float*)d_in[11];
    const float* bn1_rm = (const float*)d_in[12];
    const float* bn1_rv = (const float*)d_in[13];
    const float* mlp_W2 = (const float*)d_in[14];
    const float* mlp_b2 = (const float*)d_in[15];
    const float* bn2_g  = (const float*)d_in[16];
    const float* bn2_b  = (const float*)d_in[17];
    const float* bn2_rm = (const float*)d_in[18];
    const float* bn2_rv = (const float*)d_in[19];
    const float* eps    = (const float*)d_in[20];
    const float* ln_g   = (const float*)d_in[21];
    const float* ln_b   = (const float*)d_in[22];
    const float* out_W1 = (const float*)d_in[23];
    const float* out_b1 = (const float*)d_in[24];
    const float* out_W2 = (const float*)d_in[25];
    const float* out_b2 = (const float*)d_in[26];

    int N = in_sizes[0] / 12;
    int E = in_sizes[2] / 3;
    int B = out_size / 128 - N;
    const int* src = ei;
    const int* dst = ei + E;
    float* node_emb  = (float*)d_out;
    float* graph_emb = node_emb + (size_t)N * 128;

    float *p_z, *p_t1, *p_hcat, *p_o1;
    __half *p_wh, *p_wl;
    cudaGetSymbolAddress((void**)&p_z,    g_z);
    cudaGetSymbolAddress((void**)&p_t1,   g_t1);
    cudaGetSymbolAddress((void**)&p_hcat, g_hcat);
    cudaGetSymbolAddress((void**)&p_o1,   g_o1);
    cudaGetSymbolAddress((void**)&p_wh,   g_wth);
    cudaGetSymbolAddress((void**)&p_wl,   g_wtl);

    cudaFuncSetAttribute(k_mma<0>, cudaFuncAttributeMaxDynamicSharedMemorySize, SMEM_MMA);
    cudaFuncSetAttribute(k_mma<1>, cudaFuncAttributeMaxDynamicSharedMemorySize, SMEM_MMA);
    cudaFuncSetAttribute(k_mma<2>, cudaFuncAttributeMaxDynamicSharedMemorySize, SMEM_MMA);
    cudaFuncSetAttribute(k_mma<3>, cudaFuncAttributeMaxDynamicSharedMemorySize, SMEM_MMA);

    // weight prep (single kernel)
    k_prep_all<<<(278528 + 255) / 256, 256>>>(mlp_W1, mlp_W2, out_W1, out_W2, p_wh, p_wl);

    // input projection + CSR build
    k_in_proj<<<N, 128>>>(x, in_W, in_b);
    k_zero_deg<<<(N + 255) / 256, 256>>>(N, B);
    k_count<<<(E + 255) / 256, 256>>>(dst, E);
    int nb = (N + 511) / 512;
    k_scan1<<<nb, 512>>>(N);
    k_scan2<<<1, 256>>>(nb);
    k_scan3<<<(N + 255) / 256, 256>>>(N, E);
    k_scatter<<<(E + 255) / 256, 256>>>(src, dst, ea, E);

    int gridM = (N + 127) / 128;
    for (int l = 0; l < 3; l++) {
        k_aggregate<<<(N * 32 + 255) / 256, 256>>>(edge_W + l * 384, edge_b + l * 128, eps, l, N);
        dim3 g1(2, gridM);
        k_mma<2><<<g1, 256, SMEM_MMA>>>(p_z, 128, p_wh + l * 32768, p_wl + l * 32768, 128,
                              p_t1, 256, N,
                              mlp_b1 + l * 256, bn1_g + l * 256, bn1_b + l * 256,
                              bn1_rm + l * 256, bn1_rv + l * 256,
                              nullptr, 0, nullptr, nullptr);
        dim3 g2(1, gridM);
        k_mma<3><<<g2, 256, SMEM_MMA>>>(p_t1, 256, p_wh + 98304 + l * 32768, p_wl + 98304 + l * 32768, 256,
                              p_hcat + (l + 1) * 128, 512, N,
                              mlp_b2 + l * 128, bn2_g + l * 128, bn2_b + l * 128,
                              bn2_rm + l * 128, bn2_rv + l * 128,
                              p_hcat + l * 128, 512, ln_g + l * 128, ln_b + l * 128);
    }

    dim3 go(1, gridM);
    k_mma<1><<<go, 256, SMEM_MMA>>>(p_hcat, 512, p_wh + 196608, p_wl + 196608, 512,
                          p_o1, 128, N,
                          out_b1, nullptr, nullptr, nullptr, nullptr,
                          nullptr, 0, nullptr, nullptr);
    k_mma<0><<<go, 256, SMEM_MMA>>>(p_o1, 128, p_wh + 262144, p_wl + 262144, 128,
                          node_emb, 128, N,
                          out_b2, nullptr, nullptr, nullptr, nullptr,
                          nullptr, 0, nullptr, nullptr);

    k_pool_acc<<<(N + 63) / 64, 128>>>(node_emb, batch, N);
    k_pool_fin<<<(B * 128 + 255) / 256, 256>>>(graph_emb, B);
}

// round 9
// speedup vs baseline: 2.9147x; 1.1243x over previous
#include <cuda_runtime.h>
#include <cuda_fp16.h>
#include <cstdint>
#include <math.h>

#define MAXN 100000
#define MAXE 600000

// ---------------- scratch (no allocations allowed) ----------------
__device__ __align__(16) float  g_hcat[(size_t)MAXN * 512];   // fp32 h0|h1|h2|h3 per node
__device__ __align__(16) __half g_hh  [(size_t)MAXN * 512];   // fp16 mirror (GEMM A operand)
__device__ __align__(16) __half g_z16 [(size_t)MAXN * 128];   // fp16 z (mlp1 A)
__device__ __align__(16) __half g_t16 [(size_t)MAXN * 256];   // fp16 t1 (mlp2 A)
__device__ __align__(16) __half g_o16 [(size_t)MAXN * 128];   // fp16 o1 (out2 A)
__device__ int    g_deg   [MAXN];
__device__ int    g_rowptr[MAXN + 1];
__device__ int    g_cursor[MAXN];
__device__ int    g_bsum  [256];
__device__ int    g_boff  [256];
__device__ int    g_srcs  [MAXE];
__device__ __align__(16) float g_sattr[MAXN * 4];             // per-node sum of edge_attr (x,y,z,_)
__device__ float  g_gsum  [64 * 128];
__device__ float  g_cnt   [64];
// split fp16 weights, transposed to [N][K]
__device__ __align__(16) __half g_wth[278528];
__device__ __align__(16) __half g_wtl[278528];

// ---------------- input projection ----------------
__global__ void k_in_proj(const float* __restrict__ x, const float* __restrict__ W,
                          const float* __restrict__ b) {
    int node = blockIdx.x;
    int c = threadIdx.x;
    __shared__ float xs[12];
    if (c < 12) xs[c] = x[node * 12 + c];
    __syncthreads();
    float a = b[c];
#pragma unroll
    for (int k = 0; k < 12; k++) a += xs[k] * W[k * 128 + c];
    g_hcat[(size_t)node * 512 + c] = a;
    g_hh[(size_t)node * 512 + c] = __float2half_rn(a);
}

// ---------------- CSR build ----------------
__global__ void k_zero(int n, int b) {
    int i = blockIdx.x * blockDim.x + threadIdx.x;
    if (i < n) g_deg[i] = 0;
    if (i < n * 4) g_sattr[i] = 0.f;
    if (i < b * 128) g_gsum[i] = 0.f;
    if (i < b) g_cnt[i] = 0.f;
}
__global__ void k_count(const int* __restrict__ dst, const float* __restrict__ ea, int e) {
    int i = blockIdx.x * blockDim.x + threadIdx.x;
    if (i >= e) return;
    int d = dst[i];
    atomicAdd(&g_deg[d], 1);
    atomicAdd(&g_sattr[d * 4 + 0], ea[3 * i]);
    atomicAdd(&g_sattr[d * 4 + 1], ea[3 * i + 1]);
    atomicAdd(&g_sattr[d * 4 + 2], ea[3 * i + 2]);
}
__global__ void k_scan1(int n) {
    int t = threadIdx.x, b = blockIdx.x;
    int i = b * 512 + t;
    int v = (i < n) ? g_deg[i] : 0;
    int lane = t & 31, w = t >> 5;
    int x = v;
#pragma unroll
    for (int o = 1; o < 32; o <<= 1) {
        int y = __shfl_up_sync(0xFFFFFFFFu, x, o);
        if (lane >= o) x += y;
    }
    __shared__ int ws[16];
    if (lane == 31) ws[w] = x;
    __syncthreads();
    if (w == 0) {
        int y = (lane < 16) ? ws[lane] : 0;
#pragma unroll
        for (int o = 1; o < 16; o <<= 1) {
            int z = __shfl_up_sync(0xFFFFFFFFu, y, o);
            if (lane >= o) y += z;
        }
        if (lane < 16) ws[lane] = y;
    }
    __syncthreads();
    int incl = x + (w > 0 ? ws[w - 1] : 0);
    if (i < n) g_rowptr[i] = incl - v;
    if (t == 511) g_bsum[b] = incl;
}
__global__ void k_scan2(int nb) {
    __shared__ int s[256];
    int t = threadIdx.x;
    s[t] = (t < nb) ? g_bsum[t] : 0;
    __syncthreads();
    for (int o = 1; o < 256; o <<= 1) {
        int v = (t >= o) ? s[t - o] : 0;
        __syncthreads();
        s[t] += v;
        __syncthreads();
    }
    g_boff[t] = (t == 0) ? 0 : s[t - 1];
}
__global__ void k_scan3(int n, int e) {
    int i = blockIdx.x * blockDim.x + threadIdx.x;
    if (i < n) {
        int r = g_rowptr[i] + g_boff[i >> 9];
        g_rowptr[i] = r;
        g_cursor[i] = r;
    }
    if (i == 0) g_rowptr[n] = e;
}
__global__ void k_scatter(const int* __restrict__ src, const int* __restrict__ dst, int e) {
    int i = blockIdx.x * blockDim.x + threadIdx.x;
    if (i >= e) return;
    int p = atomicAdd(&g_cursor[dst[i]], 1);
    g_srcs[p] = src[i];
}

// ---------------- aggregation: z = (1+eps)h + sum h[src] + (sum ea)@W + deg*b ----------------
__global__ void k_aggregate(const float* __restrict__ edgeW, const float* __restrict__ edgeb,
                            const float* __restrict__ eps, int l, int n) {
    int gid = blockIdx.x * blockDim.x + threadIdx.x;
    int node = gid >> 5, lane = gid & 31;
    if (node >= n) return;
    int c = lane * 4;
    float4 w0 = *(const float4*)(edgeW + c);
    float4 w1 = *(const float4*)(edgeW + 128 + c);
    float4 w2 = *(const float4*)(edgeW + 256 + c);
    float4 eb = *(const float4*)(edgeb + c);
    float ep = 1.f + eps[l];
    const float* hb = g_hcat + (size_t)l * 128;
    float4 hh = *(const float4*)(hb + (size_t)node * 512 + c);
    float4 sa = *(const float4*)(g_sattr + node * 4);
    int j0 = g_rowptr[node], j1 = g_rowptr[node + 1];
    float dg = (float)(j1 - j0);
    float4 acc;
    acc.x = ep * hh.x + sa.x * w0.x + sa.y * w1.x + sa.z * w2.x + dg * eb.x;
    acc.y = ep * hh.y + sa.x * w0.y + sa.y * w1.y + sa.z * w2.y + dg * eb.y;
    acc.z = ep * hh.z + sa.x * w0.z + sa.y * w1.z + sa.z * w2.z + dg * eb.z;
    acc.w = ep * hh.w + sa.x * w0.w + sa.y * w1.w + sa.z * w2.w + dg * eb.w;
    for (int j = j0; j < j1; j++) {
        int s = g_srcs[j];
        float4 hs = *(const float4*)(hb + (size_t)s * 512 + c);
        acc.x += hs.x; acc.y += hs.y; acc.z += hs.z; acc.w += hs.w;
    }
    __half2 h0 = __floats2half2_rn(acc.x, acc.y);
    __half2 h1 = __floats2half2_rn(acc.z, acc.w);
    uint2 o; o.x = *(uint32_t*)&h0; o.y = *(uint32_t*)&h1;
    *(uint2*)(g_z16 + (size_t)node * 128 + c) = o;
}

// ---------------- weight prep ----------------
__global__ void k_prep_all(const float* __restrict__ W1, const float* __restrict__ W2,
                           const float* __restrict__ O1, const float* __restrict__ O2,
                           __half* __restrict__ oh, __half* __restrict__ ol) {
    int i = blockIdx.x * blockDim.x + threadIdx.x;
    if (i >= 278528) return;
    const float* src; int K, N, base, rel;
    if (i < 98304)       { int l = i / 32768; rel = i % 32768; src = W1 + (size_t)l * 32768; K = 128; N = 256; base = l * 32768; }
    else if (i < 196608) { int j = i - 98304; int l = j / 32768; rel = j % 32768; src = W2 + (size_t)l * 32768; K = 256; N = 128; base = 98304 + l * 32768; }
    else if (i < 262144) { rel = i - 196608; src = O1; K = 512; N = 128; base = 196608; }
    else                 { rel = i - 262144; src = O2; K = 128; N = 128; base = 262144; }
    int k = rel / N, n = rel % N;
    float x = src[rel];
    __half h = __float2half_rn(x);
    __half l2 = __float2half_rn(x - __half2float(h));
    oh[base + n * K + k] = h;
    ol[base + n * K + k] = l2;
}

// ---------------- tensor-core GEMM (fp16 A + split-B, full cp.async) ----------------
__device__ __forceinline__ void mma16816(float* c, const unsigned* a, const unsigned* b) {
    asm volatile(
        "mma.sync.aligned.m16n8k16.row.col.f32.f16.f16.f32 "
        "{%0,%1,%2,%3}, {%4,%5,%6,%7}, {%8,%9}, {%0,%1,%2,%3};\n"
        : "+f"(c[0]), "+f"(c[1]), "+f"(c[2]), "+f"(c[3])
        : "r"(a[0]), "r"(a[1]), "r"(a[2]), "r"(a[3]), "r"(b[0]), "r"(b[1]));
}
__device__ __forceinline__ void ldm_x4(unsigned* r, uint32_t a) {
    asm volatile("ldmatrix.sync.aligned.m8n8.x4.shared.b16 {%0,%1,%2,%3}, [%4];"
        : "=r"(r[0]), "=r"(r[1]), "=r"(r[2]), "=r"(r[3]) : "r"(a));
}
__device__ __forceinline__ uint32_t smem_u32(const void* p) {
    uint32_t a;
    asm("{ .reg .u64 t; cvta.to.shared.u64 t, %1; cvt.u32.u64 %0, t; }" : "=r"(a) : "l"(p));
    return a;
}
__device__ __forceinline__ void cpa16(uint32_t s, const void* g) {
    asm volatile("cp.async.cg.shared.global [%0], [%1], 16;" :: "r"(s), "l"(g));
}
#define CPA_COMMIT() asm volatile("cp.async.commit_group;" ::: "memory")
#define CPA_WAIT0()  asm volatile("cp.async.wait_group 0;" ::: "memory")

#define SMS 40
#define BUFB 10240u
#define OF_A(s)  ((s) * BUFB)
#define OF_BH(s) (2u * BUFB + (s) * BUFB)
#define OF_BL(s) (4u * BUFB + (s) * BUFB)
#define OF_RED   (6u * BUFB)
#define SMEM_MMA (6 * 10240 + 2048)   // 63488

// EPI: 0=+bias, 1=relu(+bias), 2=relu(BN(+bias)), 3=relu(BN(+bias))+Res+LN (grid.x==1)
// O16: store fp16 to C16 (EPI3 stores fp32 C AND fp16 C16)
template<int EPI, bool O16>
__global__ __launch_bounds__(256, 2) void k_mma(
    const __half* __restrict__ A, int lda,
    const __half* __restrict__ Wh, const __half* __restrict__ Wl, int K,
    float* __restrict__ C, __half* __restrict__ C16, int ldc, int M,
    const float* __restrict__ bias,
    const float* __restrict__ bng, const float* __restrict__ bnb,
    const float* __restrict__ bnrm, const float* __restrict__ bnrv,
    const float* __restrict__ Res, int ldr,
    const float* __restrict__ lng, const float* __restrict__ lnb) {
    extern __shared__ __align__(16) char smx[];
    uint32_t smb = smem_u32(smx);
    float* sRedP = (float*)(smx + OF_RED);

    int tid = threadIdx.x, lane = tid & 31, wid = tid >> 5;
    int wy = wid & 3, wx = wid >> 2;
    int mW = wy * 32, nW = wx * 64;
    int g = lane >> 2, qt = lane & 3;
    int rowBase = blockIdx.y * 128, colBase = blockIdx.x * 128;

    float c[2][8][4];
#pragma unroll
    for (int i = 0; i < 2; i++)
#pragma unroll
        for (int j = 0; j < 8; j++)
#pragma unroll
            for (int m = 0; m < 4; m++) c[i][j][m] = 0.f;

    uint32_t aOff = (uint32_t)((mW + (lane & 15)) * SMS + ((lane >> 4) << 3)) * 2;
    uint32_t bOff = (uint32_t)((nW + ((lane >> 4) << 3) + (lane & 7)) * SMS + (((lane >> 3) & 1) << 3)) * 2;

    // cp.async index precompute: A and B both 128 rows x 32 fp16, 2x16B per thread
    uint32_t tSm[2];
    size_t aGm[2], bGm[2];
#pragma unroll
    for (int i = 0; i < 2; i++) {
        int v = tid + i * 256;
        int r = v >> 2, kc8 = (v & 3) * 8;
        tSm[i] = (uint32_t)(r * SMS + kc8) * 2;
        int ar = rowBase + r; if (ar >= M) ar = M - 1;   // clamp (rows >= M unused)
        aGm[i] = (size_t)ar * lda + kc8;
        bGm[i] = (size_t)(colBase + r) * K + kc8;
    }

    // prologue: tile 0
#pragma unroll
    for (int i = 0; i < 2; i++) {
        cpa16(smb + OF_A(0)  + tSm[i], A  + aGm[i]);
        cpa16(smb + OF_BH(0) + tSm[i], Wh + bGm[i]);
        cpa16(smb + OF_BL(0) + tSm[i], Wl + bGm[i]);
    }
    CPA_COMMIT();

    int nk = K >> 5;
    for (int t = 0; t < nk; t++) {
        int cur = t & 1, nxt = cur ^ 1;
        CPA_WAIT0();
        __syncthreads();
        if (t + 1 < nk) {
            int k0 = (t + 1) << 5;
#pragma unroll
            for (int i = 0; i < 2; i++) {
                cpa16(smb + OF_A(nxt)  + tSm[i], A  + aGm[i] + k0);
                cpa16(smb + OF_BH(nxt) + tSm[i], Wh + bGm[i] + k0);
                cpa16(smb + OF_BL(nxt) + tSm[i], Wl + bGm[i] + k0);
            }
            CPA_COMMIT();
        }
        uint32_t aB  = smb + OF_A(cur)  + aOff;
        uint32_t bhB = smb + OF_BH(cur) + bOff;
        uint32_t blB = smb + OF_BL(cur) + bOff;
#pragma unroll
        for (int kc = 0; kc < 2; kc++) {
            uint32_t kByte = (uint32_t)(kc * 16) * 2;
            unsigned ah[2][4], bh[8][2], bl[8][2];
#pragma unroll
            for (int i = 0; i < 2; i++)
                ldm_x4(ah[i], aB + (uint32_t)(i * 16 * SMS) * 2 + kByte);
#pragma unroll
            for (int j2 = 0; j2 < 4; j2++) {
                uint32_t rb = (uint32_t)(j2 * 16 * SMS) * 2 + kByte;
                ldm_x4(&bh[j2 * 2][0], bhB + rb);
                ldm_x4(&bl[j2 * 2][0], blB + rb);
            }
#pragma unroll
            for (int i = 0; i < 2; i++)
#pragma unroll
                for (int j = 0; j < 8; j++) {
                    mma16816(c[i][j], ah[i], bh[j]);
                    mma16816(c[i][j], ah[i], bl[j]);
                }
        }
    }
    __syncthreads();

    float cs[8][2], ct[8][2];
#pragma unroll
    for (int j = 0; j < 8; j++) {
#pragma unroll
        for (int h = 0; h < 2; h++) {
            int col = colBase + nW + j * 8 + qt * 2 + h;
            if (EPI >= 2) {
                float s = bng[col] * rsqrtf(bnrv[col] + 1e-5f);
                cs[j][h] = s; ct[j][h] = bnb[col] + (bias[col] - bnrm[col]) * s;
            } else { cs[j][h] = 1.f; ct[j][h] = bias[col]; }
        }
    }

    if (EPI == 3) {
        float s[2][2], q[2][2];
#pragma unroll
        for (int i = 0; i < 2; i++) { s[i][0] = s[i][1] = 0.f; q[i][0] = q[i][1] = 0.f; }
#pragma unroll
        for (int i = 0; i < 2; i++) {
            int r1 = rowBase + mW + i * 16 + g, r2 = r1 + 8;
#pragma unroll
            for (int j = 0; j < 8; j++) {
                int colL = nW + j * 8 + qt * 2;
                float2 res1 = make_float2(0.f, 0.f), res2 = make_float2(0.f, 0.f);
                if (r1 < M) res1 = *(const float2*)(Res + (size_t)r1 * ldr + colL);
                if (r2 < M) res2 = *(const float2*)(Res + (size_t)r2 * ldr + colL);
                float v0 = fmaxf(c[i][j][0] * cs[j][0] + ct[j][0], 0.f) + res1.x;
                float v1 = fmaxf(c[i][j][1] * cs[j][1] + ct[j][1], 0.f) + res1.y;
                float v2 = fmaxf(c[i][j][2] * cs[j][0] + ct[j][0], 0.f) + res2.x;
                float v3 = fmaxf(c[i][j][3] * cs[j][1] + ct[j][1], 0.f) + res2.y;
                c[i][j][0] = v0; c[i][j][1] = v1; c[i][j][2] = v2; c[i][j][3] = v3;
                s[i][0] += v0 + v1; q[i][0] += v0 * v0 + v1 * v1;
                s[i][1] += v2 + v3; q[i][1] += v2 * v2 + v3 * v3;
            }
        }
#pragma unroll
        for (int i = 0; i < 2; i++)
#pragma unroll
            for (int h = 0; h < 2; h++) {
                s[i][h] += __shfl_xor_sync(0xFFFFFFFFu, s[i][h], 1);
                s[i][h] += __shfl_xor_sync(0xFFFFFFFFu, s[i][h], 2);
                q[i][h] += __shfl_xor_sync(0xFFFFFFFFu, q[i][h], 1);
                q[i][h] += __shfl_xor_sync(0xFFFFFFFFu, q[i][h], 2);
            }
        if (qt == 0) {
#pragma unroll
            for (int i = 0; i < 2; i++)
#pragma unroll
                for (int h = 0; h < 2; h++) {
                    int lr = mW + i * 16 + g + h * 8;
                    sRedP[lr * 2 + wx]       = s[i][h];
                    sRedP[256 + lr * 2 + wx] = q[i][h];
                }
        }
        __syncthreads();
#pragma unroll
        for (int i = 0; i < 2; i++)
#pragma unroll
            for (int h = 0; h < 2; h++) {
                int lr = mW + i * 16 + g + h * 8;
                int gr = rowBase + lr;
                float ts = sRedP[lr * 2] + sRedP[lr * 2 + 1];
                float tq = sRedP[256 + lr * 2] + sRedP[256 + lr * 2 + 1];
                float mu = ts * (1.f / 128.f);
                float var = tq * (1.f / 128.f) - mu * mu;
                float rr = rsqrtf(var + 1e-5f);
                if (gr < M) {
#pragma unroll
                    for (int j = 0; j < 8; j++) {
                        int colL = nW + j * 8 + qt * 2;
                        float2 o;
                        o.x = (c[i][j][h * 2]     - mu) * rr * lng[colL]     + lnb[colL];
                        o.y = (c[i][j][h * 2 + 1] - mu) * rr * lng[colL + 1] + lnb[colL + 1];
                        *(float2*)(C + (size_t)gr * ldc + colL) = o;
                        __half2 oh = __floats2half2_rn(o.x, o.y);
                        *(uint32_t*)(C16 + (size_t)gr * ldc + colL) = *(uint32_t*)&oh;
                    }
                }
            }
    } else {
#pragma unroll
        for (int i = 0; i < 2; i++) {
            int r1 = rowBase + mW + i * 16 + g, r2 = r1 + 8;
#pragma unroll
            for (int j = 0; j < 8; j++) {
                int col = colBase + nW + j * 8 + qt * 2;
                float o0 = c[i][j][0] * cs[j][0] + ct[j][0];
                float o1 = c[i][j][1] * cs[j][1] + ct[j][1];
                float o2 = c[i][j][2] * cs[j][0] + ct[j][0];
                float o3 = c[i][j][3] * cs[j][1] + ct[j][1];
                if (EPI >= 1) {
                    o0 = fmaxf(o0, 0.f); o1 = fmaxf(o1, 0.f);
                    o2 = fmaxf(o2, 0.f); o3 = fmaxf(o3, 0.f);
                }
                if (O16) {
                    if (r1 < M) { __half2 oh = __floats2half2_rn(o0, o1);
                        *(uint32_t*)(C16 + (size_t)r1 * ldc + col) = *(uint32_t*)&oh; }
                    if (r2 < M) { __half2 oh = __floats2half2_rn(o2, o3);
                        *(uint32_t*)(C16 + (size_t)r2 * ldc + col) = *(uint32_t*)&oh; }
                } else {
                    if (r1 < M) { float2 o; o.x = o0; o.y = o1; *(float2*)(C + (size_t)r1 * ldc + col) = o; }
                    if (r2 < M) { float2 o; o.x = o2; o.y = o3; *(float2*)(C + (size_t)r2 * ldc + col) = o; }
                }
            }
        }
    }
}

// ---------------- global mean pool ----------------
__global__ void k_pool_acc(const float* __restrict__ emb, const int* __restrict__ batch, int n) {
    int c = threadIdx.x;
    int base = blockIdx.x * 64;
    float acc = 0.f, cnt = 0.f;
    int cur = -1;
    for (int i = 0; i < 64; i++) {
        int nd = base + i;
        if (nd >= n) break;
        int g = batch[nd];
        if (g != cur) {
            if (cur >= 0) {
                atomicAdd(&g_gsum[cur * 128 + c], acc);
                if (c == 0) atomicAdd(&g_cnt[cur], cnt);
            }
            cur = g; acc = 0.f; cnt = 0.f;
        }
        acc += emb[(size_t)nd * 128 + c];
        cnt += 1.f;
    }
    if (cur >= 0) {
        atomicAdd(&g_gsum[cur * 128 + c], acc);
        if (c == 0) atomicAdd(&g_cnt[cur], cnt);
    }
}
__global__ void k_pool_fin(float* __restrict__ out, int b) {
    int i = blockIdx.x * blockDim.x + threadIdx.x;
    if (i >= b * 128) return;
    out[i] = g_gsum[i] / fmaxf(g_cnt[i >> 7], 1.f);
}

// ---------------- launch ----------------
extern "C" void kernel_launch(void* const* d_in, const int* in_sizes, int n_in,
                              void* d_out, int out_size) {
    const float* x      = (const float*)d_in[0];
    const int*   ei     = (const int*)d_in[1];
    const float* ea     = (const float*)d_in[2];
    const int*   batch  = (const int*)d_in[3];
    const float* in_W   = (const float*)d_in[4];
    const float* in_b   = (const float*)d_in[5];
    const float* edge_W = (const float*)d_in[6];
    const float* edge_b = (const float*)d_in[7];
    const float* mlp_W1 = (const float*)d_in[8];
    const float* mlp_b1 = (const float*)d_in[9];
    const float* bn1_g  = (const float*)d_in[10];
    const float* bn1_b  = (const float*)d_in[11];
    const float* bn1_rm = (const float*)d_in[12];
    const float* bn1_rv = (const float*)d_in[13];
    const float* mlp_W2 = (const float*)d_in[14];
    const float* mlp_b2 = (const float*)d_in[15];
    const float* bn2_g  = (const float*)d_in[16];
    const float* bn2_b  = (const float*)d_in[17];
    const float* bn2_rm = (const float*)d_in[18];
    const float* bn2_rv = (const float*)d_in[19];
    const float* eps    = (const float*)d_in[20];
    const float* ln_g   = (const float*)d_in[21];
    const float* ln_b   = (const float*)d_in[22];
    const float* out_W1 = (const float*)d_in[23];
    const float* out_b1 = (const float*)d_in[24];
    const float* out_W2 = (const float*)d_in[25];
    const float* out_b2 = (const float*)d_in[26];

    int N = in_sizes[0] / 12;
    int E = in_sizes[2] / 3;
    int B = out_size / 128 - N;
    const int* src = ei;
    const int* dst = ei + E;
    float* node_emb  = (float*)d_out;
    float* graph_emb = node_emb + (size_t)N * 128;

    float *p_hcat;
    __half *p_wh, *p_wl, *p_hh, *p_z16, *p_t16, *p_o16;
    cudaGetSymbolAddress((void**)&p_hcat, g_hcat);
    cudaGetSymbolAddress((void**)&p_hh,   g_hh);
    cudaGetSymbolAddress((void**)&p_z16,  g_z16);
    cudaGetSymbolAddress((void**)&p_t16,  g_t16);
    cudaGetSymbolAddress((void**)&p_o16,  g_o16);
    cudaGetSymbolAddress((void**)&p_wh,   g_wth);
    cudaGetSymbolAddress((void**)&p_wl,   g_wtl);

    cudaFuncSetAttribute(k_mma<0, false>, cudaFuncAttributeMaxDynamicSharedMemorySize, SMEM_MMA);
    cudaFuncSetAttribute(k_mma<1, true>,  cudaFuncAttributeMaxDynamicSharedMemorySize, SMEM_MMA);
    cudaFuncSetAttribute(k_mma<2, true>,  cudaFuncAttributeMaxDynamicSharedMemorySize, SMEM_MMA);
    cudaFuncSetAttribute(k_mma<3, false>, cudaFuncAttributeMaxDynamicSharedMemorySize, SMEM_MMA);

    // weight prep (single kernel)
    k_prep_all<<<(278528 + 255) / 256, 256>>>(mlp_W1, mlp_W2, out_W1, out_W2, p_wh, p_wl);

    // input projection + CSR build (+ sum of edge_attr per node)
    k_in_proj<<<N, 128>>>(x, in_W, in_b);
    k_zero<<<(N * 4 + 255) / 256, 256>>>(N, B);
    k_count<<<(E + 255) / 256, 256>>>(dst, ea, E);
    int nb = (N + 511) / 512;
    k_scan1<<<nb, 512>>>(N);
    k_scan2<<<1, 256>>>(nb);
    k_scan3<<<(N + 255) / 256, 256>>>(N, E);
    k_scatter<<<(E + 255) / 256, 256>>>(src, dst, E);

    int gridM = (N + 127) / 128;
    for (int l = 0; l < 3; l++) {
        k_aggregate<<<(N * 32 + 255) / 256, 256>>>(edge_W + l * 384, edge_b + l * 128, eps, l, N);
        dim3 g1(2, gridM);
        k_mma<2, true><<<g1, 256, SMEM_MMA>>>(p_z16, 128, p_wh + l * 32768, p_wl + l * 32768, 128,
                              nullptr, p_t16, 256, N,
                              mlp_b1 + l * 256, bn1_g + l * 256, bn1_b + l * 256,
                              bn1_rm + l * 256, bn1_rv + l * 256,
                              nullptr, 0, nullptr, nullptr);
        dim3 g2(1, gridM);
        k_mma<3, false><<<g2, 256, SMEM_MMA>>>(p_t16, 256, p_wh + 98304 + l * 32768, p_wl + 98304 + l * 32768, 256,
                              p_hcat + (l + 1) * 128, p_hh + (l + 1) * 128, 512, N,
                              mlp_b2 + l * 128, bn2_g + l * 128, bn2_b + l * 128,
                              bn2_rm + l * 128, bn2_rv + l * 128,
                              p_hcat + l * 128, 512, ln_g + l * 128, ln_b + l * 128);
    }

    dim3 go(1, gridM);
    k_mma<1, true><<<go, 256, SMEM_MMA>>>(p_hh, 512, p_wh + 196608, p_wl + 196608, 512,
                          nullptr, p_o16, 128, N,
                          out_b1, nullptr, nullptr, nullptr, nullptr,
                          nullptr, 0, nullptr, nullptr);
    k_mma<0, false><<<go, 256, SMEM_MMA>>>(p_o16, 128, p_wh + 262144, p_wl + 262144, 128,
                          node_emb, nullptr, 128, N,
                          out_b2, nullptr, nullptr, nullptr, nullptr,
                          nullptr, 0, nullptr, nullptr);

    k_pool_acc<<<(N + 63) / 64, 128>>>(node_emb, batch, N);
    k_pool_fin<<<(B * 128 + 255) / 256, 256>>>(graph_emb, B);
}